// round 14
// baseline (speedup 1.0000x reference)
#include <cuda_runtime.h>
#include <cuda_bf16.h>
#include <cstdint>

#define N_NODES 50000
#define E_EDGES 600000
#define D 128
#define P_PAIRS 131072
#define O_OUT 7
#define NT64 782                             // ceil(N/64)

#define HROW_U32 68
#define HARR_U32 (64 * HROW_U32)
#define HARR_BYTES (HARR_U32 * 4)
#define WARR_U32 (128 * HROW_U32)
#define WARR_BYTES (WARR_U32 * 4)
#define SMEM_MLP (4 * HARR_BYTES + 4 * WARR_BYTES)
#define SMEM_GL  (4 * HARR_BYTES + 2 * WARR_BYTES)

// Scratch
__device__ float g_t[N_NODES * D];
__device__ float g_h[N_NODES * D];
__device__ float g_colsum[D];
__device__ float g_colsq[D];
__device__ float g_bn[2 * D];
__device__ __nv_bfloat16 g_wh[5 * D * D];
__device__ __nv_bfloat16 g_wl[5 * D * D];
// CSR (rebuilt every launch)
__device__ int g_deg[N_NODES];
__device__ int g_off[N_NODES + 1];
__device__ int g_cur[N_NODES];
__device__ int g_elist[E_EDGES];

// ---------------------------------------------------------------------------
// prep: split weights; zero deg + stats
// ---------------------------------------------------------------------------
__global__ void k_prep_w(const float* __restrict__ w0, const float* __restrict__ w1,
                         const float* __restrict__ w2, const float* __restrict__ w3,
                         const float* __restrict__ w4) {
    int i = blockIdx.x * blockDim.x + threadIdx.x;
    if (i < N_NODES) g_deg[i] = 0;
    if (i < D) { g_colsum[i] = 0.f; g_colsq[i] = 0.f; }
    if (i >= 5 * D * D) return;
    const float* srcs[5] = {w0, w1, w2, w3, w4};
    float v = srcs[i >> 14][i & 16383];
    __nv_bfloat16 h = __float2bfloat16(v);
    g_wh[i] = h;
    g_wl[i] = __float2bfloat16(v - __bfloat162float(h));
}

__global__ void k_hist(const int* __restrict__ dst) {
    int e = blockIdx.x * blockDim.x + threadIdx.x;
    if (e < E_EDGES) atomicAdd(&g_deg[dst[e]], 1);
}

// single block, 1024 threads: exclusive scan of g_deg -> g_off, g_cur
__global__ void __launch_bounds__(1024) k_scan() {
    __shared__ int s_tot[1024];
    const int CH = (N_NODES + 1023) / 1024;
    int t = threadIdx.x;
    int base = t * CH;
    int sum = 0;
    for (int i = 0; i < CH; i++) {
        int idx = base + i;
        if (idx < N_NODES) sum += g_deg[idx];
    }
    s_tot[t] = sum;
    __syncthreads();
    for (int off = 1; off < 1024; off <<= 1) {
        int v = 0;
        if (t >= off) v = s_tot[t - off];
        __syncthreads();
        if (t >= off) s_tot[t] += v;
        __syncthreads();
    }
    int run = (t == 0) ? 0 : s_tot[t - 1];
    for (int i = 0; i < CH; i++) {
        int idx = base + i;
        if (idx < N_NODES) {
            g_off[idx] = run;
            g_cur[idx] = run;
            run += g_deg[idx];
        }
    }
    if (t == 1023) g_off[N_NODES] = s_tot[1023];
}

__global__ void k_fill(const int* __restrict__ src, const int* __restrict__ dst) {
    int e = blockIdx.x * blockDim.x + threadIdx.x;
    if (e >= E_EDGES) return;
    int pos = atomicAdd(&g_cur[dst[e]], 1);
    g_elist[pos] = src[e];
}

// ---------------------------------------------------------------------------
// MMA helpers
// ---------------------------------------------------------------------------
static __device__ __forceinline__ uint32_t smem_u32(const void* p) {
    return (uint32_t)__cvta_generic_to_shared(p);
}
static __device__ __forceinline__ void split2(float a, float b, uint32_t& hi, uint32_t& lo) {
    __nv_bfloat162 h = __floats2bfloat162_rn(a, b);
    float ra = a - __bfloat162float(h.x);
    float rb = b - __bfloat162float(h.y);
    __nv_bfloat162 l = __floats2bfloat162_rn(ra, rb);
    hi = *reinterpret_cast<uint32_t*>(&h);
    lo = *reinterpret_cast<uint32_t*>(&l);
}
static __device__ __forceinline__ void ldmx4(uint32_t addr, uint32_t r[4]) {
    asm("ldmatrix.sync.aligned.m8n8.x4.shared.b16 {%0,%1,%2,%3}, [%4];"
        : "=r"(r[0]), "=r"(r[1]), "=r"(r[2]), "=r"(r[3]) : "r"(addr) : "memory");
}
static __device__ __forceinline__ void mma16816(float c[4], const uint32_t a[4],
                                                uint32_t b0, uint32_t b1) {
    asm("mma.sync.aligned.m16n8k16.row.col.f32.bf16.bf16.f32 "
        "{%0,%1,%2,%3},{%4,%5,%6,%7},{%8,%9},{%0,%1,%2,%3};"
        : "+f"(c[0]), "+f"(c[1]), "+f"(c[2]), "+f"(c[3])
        : "r"(a[0]), "r"(a[1]), "r"(a[2]), "r"(a[3]), "r"(b0), "r"(b1));
}
static __device__ __forceinline__ void cpa16(uint32_t dst, const void* src) {
    asm volatile("cp.async.cg.shared.global [%0], [%1], 16;"
                 :: "r"(dst), "l"(src) : "memory");
}
static __device__ __forceinline__ void barg(int id) {
    asm volatile("bar.sync %0, 256;" :: "r"(id) : "memory");
}

static __device__ __forceinline__ void mma_3pass(float acc[2][4][4],
                                                 uint32_t Ahi, uint32_t Alo,
                                                 uint32_t Bhi, uint32_t Blo,
                                                 const uint32_t aoff[2],
                                                 const uint32_t boff[2]) {
#pragma unroll
    for (int ks = 0; ks < 8; ks++) {
        uint32_t kb = ks * 32;
        uint32_t ah[2][4], al[2][4], bh[2][4], bl[2][4];
#pragma unroll
        for (int mt = 0; mt < 2; mt++) {
            ldmx4(Ahi + aoff[mt] + kb, ah[mt]);
            ldmx4(Alo + aoff[mt] + kb, al[mt]);
        }
#pragma unroll
        for (int np = 0; np < 2; np++) {
            ldmx4(Bhi + boff[np] + kb, bh[np]);
            ldmx4(Blo + boff[np] + kb, bl[np]);
        }
#pragma unroll
        for (int mt = 0; mt < 2; mt++)
#pragma unroll
            for (int nt = 0; nt < 4; nt++) {
                int np = nt >> 1, o = (nt & 1) * 2;
                mma16816(acc[mt][nt], ah[mt], bh[np][o], bh[np][o + 1]);
            }
#pragma unroll
        for (int mt = 0; mt < 2; mt++)
#pragma unroll
            for (int nt = 0; nt < 4; nt++) {
                int np = nt >> 1, o = (nt & 1) * 2;
                mma16816(acc[mt][nt], ah[mt], bl[np][o], bl[np][o + 1]);
            }
#pragma unroll
        for (int mt = 0; mt < 2; mt++)
#pragma unroll
            for (int nt = 0; nt < 4; nt++) {
                int np = nt >> 1, o = (nt & 1) * 2;
                mma16816(acc[mt][nt], al[mt], bh[np][o], bh[np][o + 1]);
            }
    }
}

static __device__ __forceinline__ void stage_W(const __nv_bfloat16* __restrict__ w,
                                               uint32_t dbase, int t) {
#pragma unroll
    for (int it = 0; it < 4; it++) {
        int c = t + it * 512;
        int row = c >> 4, j = c & 15;
        cpa16(dbase + row * 272 + j * 16, w + row * D + j * 8);
    }
}

static __device__ __forceinline__ void prefetch_A(const float* __restrict__ A,
                                                  int gr, int sq, float4 px[8]) {
    if (gr < N_NODES) {
        const float4* Ar = reinterpret_cast<const float4*>(A + (size_t)gr * D);
#pragma unroll
        for (int j = 0; j < 8; j++) px[j] = Ar[sq * 8 + j];
    }
}

// ---------------------------------------------------------------------------
// Persistent fused GIN layer with IN-STAGE neighbor gather.
// Reads A (input activations; NEVER aliases out), writes out.
// A_comb = AFF ? a⊙(cA·x + Σh) + (cA+deg)·c  :  cA·x + Σh
// ---------------------------------------------------------------------------
template <int AFF>
__global__ void __launch_bounds__(512) k_mlp(const float* __restrict__ A,
                                             const float* __restrict__ epsp,
                                             const float* __restrict__ b1,
                                             const float* __restrict__ b2,
                                             const __nv_bfloat16* __restrict__ w1h,
                                             const __nv_bfloat16* __restrict__ w1l,
                                             const __nv_bfloat16* __restrict__ w2h,
                                             const __nv_bfloat16* __restrict__ w2l,
                                             float* __restrict__ out) {
    extern __shared__ uint32_t smem[];
    __shared__ float sb1[D], sb2[D], s_sum[D], s_sq[D];

    const int t = threadIdx.x;
    const int grp = t >> 8;
    const int t2 = t & 255;
    const int warp8 = t2 >> 5, lane = t & 31;
    const int wm = warp8 & 1, wn = warp8 >> 1;
    const float cA = 1.0f + *epsp;

    uint32_t* As_hi = smem + grp * 2 * HARR_U32;
    uint32_t* As_lo = As_hi + HARR_U32;
    uint32_t* wbase = smem + 4 * HARR_U32;

    if (t < D) {
        sb1[t] = __ldg(b1 + t);
        sb2[t] = __ldg(b2 + t);
        s_sum[t] = 0.f;
        s_sq[t] = 0.f;
    }

    const uint32_t W1h = smem_u32(wbase);
    const uint32_t W1l = smem_u32(wbase + WARR_U32 * 1);
    const uint32_t W2h = smem_u32(wbase + WARR_U32 * 2);
    const uint32_t W2l = smem_u32(wbase + WARR_U32 * 3);
    stage_W(w1h, W1h, t);
    stage_W(w1l, W1l, t);
    stage_W(w2h, W2h, t);
    stage_W(w2l, W2l, t);
    asm volatile("cp.async.commit_group;" ::: "memory");

    uint32_t aoff[2], boff[2];
#pragma unroll
    for (int mt = 0; mt < 2; mt++) {
        int row = wm * 32 + mt * 16 + ((lane >> 3) & 1) * 8 + (lane & 7);
        aoff[mt] = row * 272 + (lane >> 4) * 16;
    }
#pragma unroll
    for (int np = 0; np < 2; np++) {
        int row = wn * 32 + np * 16 + (lane >> 4) * 8 + (lane & 7);
        boff[np] = row * 272 + ((lane >> 3) & 1) * 16;
    }
    const uint32_t Ahi = smem_u32(As_hi), Alo = smem_u32(As_lo);
    const int lg = lane >> 2;
    const int c2 = (lane & 3) * 2;
    const int srow = t2 >> 2, sq = t2 & 3;
    const int bid = 1 + grp;

    int tile = blockIdx.x * 2 + grp;
    const int step = gridDim.x * 2;
    float4 px[8];
    prefetch_A(A, tile * 64 + srow, sq, px);
    asm volatile("cp.async.wait_group 0;" ::: "memory");
    __syncthreads();

    for (; tile < NT64; tile += step) {
        const int row0 = tile * 64;
        const int gr = row0 + srow;

        // stage: px = cA*x; += Σ h[src]; optional affine fold; split to smem
        {
            if (gr < N_NODES) {
                const int beg = g_off[gr];
                const int end = g_off[gr + 1];
#pragma unroll
                for (int j = 0; j < 8; j++) {
                    px[j].x *= cA; px[j].y *= cA; px[j].z *= cA; px[j].w *= cA;
                }
                for (int i = beg; i < end; i++) {
                    int s = g_elist[i];
                    const float4* Hs = reinterpret_cast<const float4*>(A + (size_t)s * D);
#pragma unroll
                    for (int j = 0; j < 8; j++) {
                        float4 hv = Hs[sq * 8 + j];
                        px[j].x += hv.x; px[j].y += hv.y;
                        px[j].z += hv.z; px[j].w += hv.w;
                    }
                }
                if (AFF) {
                    float f = cA + (float)(end - beg);
#pragma unroll
                    for (int j = 0; j < 8; j++) {
                        int f4 = sq * 8 + j;
                        float4 a = *reinterpret_cast<const float4*>(g_bn + f4 * 4);
                        float4 c = *reinterpret_cast<const float4*>(g_bn + D + f4 * 4);
                        px[j].x = a.x * px[j].x + f * c.x;
                        px[j].y = a.y * px[j].y + f * c.y;
                        px[j].z = a.z * px[j].z + f * c.z;
                        px[j].w = a.w * px[j].w + f * c.w;
                    }
                }
            } else {
#pragma unroll
                for (int j = 0; j < 8; j++)
                    px[j] = make_float4(0.f, 0.f, 0.f, 0.f);
            }
#pragma unroll
            for (int j = 0; j < 8; j++) {
                uint32_t h0, l0, h1, l1;
                split2(px[j].x, px[j].y, h0, l0);
                split2(px[j].z, px[j].w, h1, l1);
                int o = srow * HROW_U32 + (sq * 8 + j) * 2;
                *reinterpret_cast<uint2*>(&As_hi[o]) = make_uint2(h0, h1);
                *reinterpret_cast<uint2*>(&As_lo[o]) = make_uint2(l0, l1);
            }
        }
        barg(bid);

        float acc[2][4][4];
#pragma unroll
        for (int mt = 0; mt < 2; mt++)
#pragma unroll
            for (int nt = 0; nt < 4; nt++)
#pragma unroll
                for (int i = 0; i < 4; i++) acc[mt][nt][i] = 0.f;

        // ---- GEMM1 ----
        mma_3pass(acc, Ahi, Alo, W1h, W1l, aoff, boff);

        const int ntile = tile + step;
        if (ntile < NT64) prefetch_A(A, ntile * 64 + srow, sq, px);

        barg(bid);

        // epilogue1: P = relu(acc+b1) -> bf16 hi/lo back into As
#pragma unroll
        for (int mt = 0; mt < 2; mt++) {
            int ra = wm * 32 + mt * 16 + lg;
            int rb = ra + 8;
#pragma unroll
            for (int nt = 0; nt < 4; nt++) {
                int col = wn * 32 + nt * 8 + c2;
                int o = col >> 1;
                float t0 = fmaxf(acc[mt][nt][0] + sb1[col], 0.f);
                float t1 = fmaxf(acc[mt][nt][1] + sb1[col + 1], 0.f);
                float t2v = fmaxf(acc[mt][nt][2] + sb1[col], 0.f);
                float t3 = fmaxf(acc[mt][nt][3] + sb1[col + 1], 0.f);
                uint32_t hi, lo;
                split2(t0, t1, hi, lo);
                As_hi[ra * HROW_U32 + o] = hi;
                As_lo[ra * HROW_U32 + o] = lo;
                split2(t2v, t3, hi, lo);
                As_hi[rb * HROW_U32 + o] = hi;
                As_lo[rb * HROW_U32 + o] = lo;
#pragma unroll
                for (int i = 0; i < 4; i++) acc[mt][nt][i] = 0.f;
            }
        }
        barg(bid);

        // ---- GEMM2 ----
        mma_3pass(acc, Ahi, Alo, W2h, W2l, aoff, boff);
        barg(bid);

        // epilogue2: relu+bias, store h, accumulate column stats
        {
            float sp[4][2], qp[4][2];
#pragma unroll
            for (int nt = 0; nt < 4; nt++) {
                sp[nt][0] = sp[nt][1] = 0.f;
                qp[nt][0] = qp[nt][1] = 0.f;
            }
#pragma unroll
            for (int mt = 0; mt < 2; mt++) {
                int ra = row0 + wm * 32 + mt * 16 + lg;
                int rb = ra + 8;
#pragma unroll
                for (int nt = 0; nt < 4; nt++) {
                    int col = wn * 32 + nt * 8 + c2;
                    float v0 = fmaxf(acc[mt][nt][0] + sb2[col], 0.f);
                    float v1 = fmaxf(acc[mt][nt][1] + sb2[col + 1], 0.f);
                    float v2 = fmaxf(acc[mt][nt][2] + sb2[col], 0.f);
                    float v3 = fmaxf(acc[mt][nt][3] + sb2[col + 1], 0.f);
                    if (ra < N_NODES) {
                        *reinterpret_cast<float2*>(out + (size_t)ra * D + col) =
                            make_float2(v0, v1);
                        sp[nt][0] += v0; sp[nt][1] += v1;
                        qp[nt][0] += v0 * v0; qp[nt][1] += v1 * v1;
                    }
                    if (rb < N_NODES) {
                        *reinterpret_cast<float2*>(out + (size_t)rb * D + col) =
                            make_float2(v2, v3);
                        sp[nt][0] += v2; sp[nt][1] += v3;
                        qp[nt][0] += v2 * v2; qp[nt][1] += v3 * v3;
                    }
                }
            }
#pragma unroll
            for (int nt = 0; nt < 4; nt++) {
#pragma unroll
                for (int d = 4; d < 32; d <<= 1) {
                    sp[nt][0] += __shfl_xor_sync(0xffffffffu, sp[nt][0], d);
                    sp[nt][1] += __shfl_xor_sync(0xffffffffu, sp[nt][1], d);
                    qp[nt][0] += __shfl_xor_sync(0xffffffffu, qp[nt][0], d);
                    qp[nt][1] += __shfl_xor_sync(0xffffffffu, qp[nt][1], d);
                }
            }
            if (lg == 0) {
#pragma unroll
                for (int nt = 0; nt < 4; nt++) {
                    int col = wn * 32 + nt * 8 + c2;
                    atomicAdd(&s_sum[col], sp[nt][0]);
                    atomicAdd(&s_sum[col + 1], sp[nt][1]);
                    atomicAdd(&s_sq[col], qp[nt][0]);
                    atomicAdd(&s_sq[col + 1], qp[nt][1]);
                }
            }
        }
    }

    __syncthreads();
    if (t < D) {
        asm volatile("red.global.add.f32 [%0], %1;" :: "l"(&g_colsum[t]), "f"(s_sum[t]) : "memory");
        asm volatile("red.global.add.f32 [%0], %1;" :: "l"(&g_colsq[t]), "f"(s_sq[t]) : "memory");
    }
}

// ---------------------------------------------------------------------------
// Persistent final linear, dual-group (reads A, writes out; A != out)
// ---------------------------------------------------------------------------
__global__ void __launch_bounds__(512) k_gemm_l(const float* __restrict__ A,
                                                const float* __restrict__ bias,
                                                const __nv_bfloat16* __restrict__ wh,
                                                const __nv_bfloat16* __restrict__ wl,
                                                float* __restrict__ out) {
    extern __shared__ uint32_t smem[];
    __shared__ float sb[D];

    const int t = threadIdx.x;
    const int grp = t >> 8;
    const int t2 = t & 255;
    const int warp8 = t2 >> 5, lane = t & 31;
    const int wm = warp8 & 1, wn = warp8 >> 1;

    uint32_t* As_hi = smem + grp * 2 * HARR_U32;
    uint32_t* As_lo = As_hi + HARR_U32;
    uint32_t* wbase = smem + 4 * HARR_U32;

    if (t < D) sb[t] = __ldg(bias + t);

    const uint32_t Wh = smem_u32(wbase);
    const uint32_t Wl = smem_u32(wbase + WARR_U32);
    stage_W(wh, Wh, t);
    stage_W(wl, Wl, t);
    asm volatile("cp.async.commit_group;" ::: "memory");

    uint32_t aoff[2], boff[2];
#pragma unroll
    for (int mt = 0; mt < 2; mt++) {
        int row = wm * 32 + mt * 16 + ((lane >> 3) & 1) * 8 + (lane & 7);
        aoff[mt] = row * 272 + (lane >> 4) * 16;
    }
#pragma unroll
    for (int np = 0; np < 2; np++) {
        int row = wn * 32 + np * 16 + (lane >> 4) * 8 + (lane & 7);
        boff[np] = row * 272 + ((lane >> 3) & 1) * 16;
    }
    const uint32_t Ahi = smem_u32(As_hi), Alo = smem_u32(As_lo);
    const int lg = lane >> 2;
    const int c2 = (lane & 3) * 2;
    const int srow = t2 >> 2, sq = t2 & 3;
    const int bid = 1 + grp;

    int tile = blockIdx.x * 2 + grp;
    const int step = gridDim.x * 2;
    float4 px[8];
    prefetch_A(A, tile * 64 + srow, sq, px);
    asm volatile("cp.async.wait_group 0;" ::: "memory");
    __syncthreads();

    for (; tile < NT64; tile += step) {
        const int row0 = tile * 64;
        const int gr = row0 + srow;

#pragma unroll
        for (int j = 0; j < 8; j++) {
            int f4 = sq * 8 + j;
            float4 v = make_float4(0.f, 0.f, 0.f, 0.f);
            if (gr < N_NODES) {
                v = px[j];
                float4 a = *reinterpret_cast<const float4*>(g_bn + f4 * 4);
                float4 c = *reinterpret_cast<const float4*>(g_bn + D + f4 * 4);
                v.x = a.x * v.x + c.x; v.y = a.y * v.y + c.y;
                v.z = a.z * v.z + c.z; v.w = a.w * v.w + c.w;
            }
            uint32_t h0, l0, h1, l1;
            split2(v.x, v.y, h0, l0);
            split2(v.z, v.w, h1, l1);
            int o = srow * HROW_U32 + f4 * 2;
            *reinterpret_cast<uint2*>(&As_hi[o]) = make_uint2(h0, h1);
            *reinterpret_cast<uint2*>(&As_lo[o]) = make_uint2(l0, l1);
        }
        barg(bid);

        float acc[2][4][4];
#pragma unroll
        for (int mt = 0; mt < 2; mt++)
#pragma unroll
            for (int nt = 0; nt < 4; nt++)
#pragma unroll
                for (int i = 0; i < 4; i++) acc[mt][nt][i] = 0.f;

        mma_3pass(acc, Ahi, Alo, Wh, Wl, aoff, boff);

        const int ntile = tile + step;
        if (ntile < NT64) prefetch_A(A, ntile * 64 + srow, sq, px);

        barg(bid);

#pragma unroll
        for (int mt = 0; mt < 2; mt++) {
            int ra = row0 + wm * 32 + mt * 16 + lg;
            int rb = ra + 8;
#pragma unroll
            for (int nt = 0; nt < 4; nt++) {
                int col = wn * 32 + nt * 8 + c2;
                if (ra < N_NODES)
                    *reinterpret_cast<float2*>(out + (size_t)ra * D + col) =
                        make_float2(fmaxf(acc[mt][nt][0] + sb[col], 0.f),
                                    fmaxf(acc[mt][nt][1] + sb[col + 1], 0.f));
                if (rb < N_NODES)
                    *reinterpret_cast<float2*>(out + (size_t)rb * D + col) =
                        make_float2(fmaxf(acc[mt][nt][2] + sb[col], 0.f),
                                    fmaxf(acc[mt][nt][3] + sb[col + 1], 0.f));
            }
        }
    }
}

// ---------------------------------------------------------------------------
__global__ void k_bnprep(const float* __restrict__ gamma,
                         const float* __restrict__ beta) {
    int t = threadIdx.x;
    float inv_n = 1.0f / (float)N_NODES;
    float mu = g_colsum[t] * inv_n;
    float var = g_colsq[t] * inv_n - mu * mu;
    float a = gamma[t] * rsqrtf(var + 1e-5f);
    g_bn[t] = a;
    g_bn[D + t] = beta[t] - mu * a;
    g_colsum[t] = 0.f;
    g_colsq[t] = 0.f;
}

// ---------------------------------------------------------------------------
__global__ void __launch_bounds__(256) k_pairs(const float* __restrict__ h,
                                               const int* __restrict__ pairs,
                                               const float* __restrict__ Wfc,
                                               const float* __restrict__ bfc,
                                               float* __restrict__ out) {
    __shared__ float sW[O_OUT][D];
    __shared__ float sb[O_OUT];
    int t = threadIdx.x;
    for (int i = t; i < O_OUT * D; i += 256) sW[i / D][i % D] = Wfc[i];
    if (t < O_OUT) sb[t] = bfc[t];
    __syncthreads();

    int p = (blockIdx.x * 256 + t) >> 5;
    int lane = t & 31;
    if (p >= P_PAIRS) return;

    int i0 = pairs[2 * p];
    int i1 = pairs[2 * p + 1];
    float4 u = reinterpret_cast<const float4*>(h + (size_t)i0 * D)[lane];
    float4 v = reinterpret_cast<const float4*>(h + (size_t)i1 * D)[lane];
    float4 w = make_float4(u.x * v.x, u.y * v.y, u.z * v.z, u.w * v.w);

    float s[O_OUT];
#pragma unroll
    for (int o = 0; o < O_OUT; o++)
        s[o] = w.x * sW[o][4 * lane + 0] + w.y * sW[o][4 * lane + 1] +
               w.z * sW[o][4 * lane + 2] + w.w * sW[o][4 * lane + 3];
#pragma unroll
    for (int o = 0; o < O_OUT; o++)
#pragma unroll
        for (int off = 16; off > 0; off >>= 1)
            s[o] += __shfl_xor_sync(0xffffffffu, s[o], off);
    if (lane == 0)
#pragma unroll
        for (int o = 0; o < O_OUT; o++) out[(size_t)p * O_OUT + o] = s[o] + sb[o];
}

// ---------------------------------------------------------------------------
extern "C" void kernel_launch(void* const* d_in, const int* in_sizes, int n_in,
                              void* d_out, int out_size) {
    const float* x    = (const float*)d_in[0];
    const float* W1a  = (const float*)d_in[1];
    const float* b1a  = (const float*)d_in[2];
    const float* W2a  = (const float*)d_in[3];
    const float* b2a  = (const float*)d_in[4];
    const float* g0   = (const float*)d_in[5];
    const float* bt0  = (const float*)d_in[6];
    const float* eps0 = (const float*)d_in[7];
    const float* W1b  = (const float*)d_in[8];
    const float* b1b  = (const float*)d_in[9];
    const float* W2b  = (const float*)d_in[10];
    const float* b2b  = (const float*)d_in[11];
    const float* g1   = (const float*)d_in[12];
    const float* bt1  = (const float*)d_in[13];
    const float* eps1 = (const float*)d_in[14];
    const float* Wl   = (const float*)d_in[15];
    const float* bl   = (const float*)d_in[16];
    const float* Wfc  = (const float*)d_in[17];
    const float* bfc  = (const float*)d_in[18];
    const int* esrc   = (const int*)d_in[19];
    const int* edst   = (const int*)d_in[20];
    const int* pairs  = (const int*)d_in[21];
    float* out = (float*)d_out;

    float *t, *h;
    __nv_bfloat16 *wh, *wl;
    cudaGetSymbolAddress((void**)&t, g_t);
    cudaGetSymbolAddress((void**)&h, g_h);
    cudaGetSymbolAddress((void**)&wh, g_wh);
    cudaGetSymbolAddress((void**)&wl, g_wl);

    cudaFuncSetAttribute(k_mlp<0>, cudaFuncAttributeMaxDynamicSharedMemorySize, SMEM_MLP);
    cudaFuncSetAttribute(k_mlp<1>, cudaFuncAttributeMaxDynamicSharedMemorySize, SMEM_MLP);
    cudaFuncSetAttribute(k_gemm_l, cudaFuncAttributeMaxDynamicSharedMemorySize, SMEM_GL);

    const int EB = (E_EDGES + 255) / 256;
    const int PB = (P_PAIRS * 32) / 256;
    const int WS = D * D;
    const int PG = 148;

    // prep + CSR build
    k_prep_w<<<(5 * WS + 255) / 256, 256>>>(W1a, W2a, W1b, W2b, Wl);
    k_hist<<<EB, 256>>>(edst);
    k_scan<<<1, 1024>>>();
    k_fill<<<EB, 256>>>(esrc, edst);

    // Layer A: x -> h (gather of x fused into stage)
    k_mlp<0><<<PG, 512, SMEM_MLP>>>(x, eps0, b1a, b2a,
                                    wh + 0 * WS, wl + 0 * WS,
                                    wh + 1 * WS, wl + 1 * WS, h);
    k_bnprep<<<1, 128>>>(g0, bt0);

    // Layer B: h -> t (PING-PONG: never in-place with fused gather)
    k_mlp<1><<<PG, 512, SMEM_MLP>>>(h, eps1, b1b, b2b,
                                    wh + 2 * WS, wl + 2 * WS,
                                    wh + 3 * WS, wl + 3 * WS, t);
    k_bnprep<<<1, 128>>>(g1, bt1);

    // Final linear: t -> h (h is dead; no gather so per-row only)
    k_gemm_l<<<PG, 512, SMEM_GL>>>(t, bl, wh + 4 * WS, wl + 4 * WS, h);
    k_pairs<<<PB, 256>>>(h, pairs, Wfc, bfc, out);
}

// round 15
// speedup vs baseline: 1.5031x; 1.5031x over previous
#include <cuda_runtime.h>
#include <cuda_bf16.h>
#include <cstdint>

#define N_NODES 50000
#define E_EDGES 600000
#define D 128
#define P_PAIRS 131072
#define O_OUT 7
#define NT64 782                             // ceil(N/64)
#define NPAD (NT64 * 64)                     // 50048

#define HROW_U32 68
#define HARR_U32 (64 * HROW_U32)
#define HARR_BYTES (HARR_U32 * 4)
#define WARR_U32 (128 * HROW_U32)
#define WARR_BYTES (WARR_U32 * 4)
#define SMEM_MLP (4 * HARR_BYTES + 4 * WARR_BYTES)
#define SMEM_GL  (4 * HARR_BYTES + 2 * WARR_BYTES)

// Scratch
__device__ float g_t[N_NODES * D];
__device__ float g_h[N_NODES * D];
__device__ float g_colsum[D];
__device__ float g_colsq[D];
__device__ float g_bn[2 * D];
__device__ __nv_bfloat16 g_wh[5 * D * D];
__device__ __nv_bfloat16 g_wl[5 * D * D];
__device__ __nv_bfloat16 g_ahi[NPAD * D];    // pre-split combined MLP input (hi)
__device__ __nv_bfloat16 g_alo[NPAD * D];    // (lo)
// CSR (rebuilt every launch)
__device__ int g_deg[N_NODES];
__device__ int g_off[N_NODES + 1];
__device__ int g_cur[N_NODES];
__device__ int g_elist[E_EDGES];

// ---------------------------------------------------------------------------
__global__ void k_prep_w(const float* __restrict__ w0, const float* __restrict__ w1,
                         const float* __restrict__ w2, const float* __restrict__ w3,
                         const float* __restrict__ w4) {
    int i = blockIdx.x * blockDim.x + threadIdx.x;
    if (i < N_NODES) g_deg[i] = 0;
    if (i < D) { g_colsum[i] = 0.f; g_colsq[i] = 0.f; }
    if (i >= 5 * D * D) return;
    const float* srcs[5] = {w0, w1, w2, w3, w4};
    float v = srcs[i >> 14][i & 16383];
    __nv_bfloat16 h = __float2bfloat16(v);
    g_wh[i] = h;
    g_wl[i] = __float2bfloat16(v - __bfloat162float(h));
}

__global__ void k_hist(const int* __restrict__ dst) {
    int e = blockIdx.x * blockDim.x + threadIdx.x;
    if (e < E_EDGES) atomicAdd(&g_deg[dst[e]], 1);
}

__global__ void __launch_bounds__(1024) k_scan() {
    __shared__ int s_tot[1024];
    const int CH = (N_NODES + 1023) / 1024;
    int t = threadIdx.x;
    int base = t * CH;
    int sum = 0;
    for (int i = 0; i < CH; i++) {
        int idx = base + i;
        if (idx < N_NODES) sum += g_deg[idx];
    }
    s_tot[t] = sum;
    __syncthreads();
    for (int off = 1; off < 1024; off <<= 1) {
        int v = 0;
        if (t >= off) v = s_tot[t - off];
        __syncthreads();
        if (t >= off) s_tot[t] += v;
        __syncthreads();
    }
    int run = (t == 0) ? 0 : s_tot[t - 1];
    for (int i = 0; i < CH; i++) {
        int idx = base + i;
        if (idx < N_NODES) {
            g_off[idx] = run;
            g_cur[idx] = run;
            run += g_deg[idx];
        }
    }
    if (t == 1023) g_off[N_NODES] = s_tot[1023];
}

__global__ void k_fill(const int* __restrict__ src, const int* __restrict__ dst) {
    int e = blockIdx.x * blockDim.x + threadIdx.x;
    if (e >= E_EDGES) return;
    int pos = atomicAdd(&g_cur[dst[e]], 1);
    g_elist[pos] = src[e];
}

// ---------------------------------------------------------------------------
static __device__ __forceinline__ uint32_t smem_u32(const void* p) {
    return (uint32_t)__cvta_generic_to_shared(p);
}
static __device__ __forceinline__ void split2(float a, float b, uint32_t& hi, uint32_t& lo) {
    __nv_bfloat162 h = __floats2bfloat162_rn(a, b);
    float ra = a - __bfloat162float(h.x);
    float rb = b - __bfloat162float(h.y);
    __nv_bfloat162 l = __floats2bfloat162_rn(ra, rb);
    hi = *reinterpret_cast<uint32_t*>(&h);
    lo = *reinterpret_cast<uint32_t*>(&l);
}
static __device__ __forceinline__ void ldmx4(uint32_t addr, uint32_t r[4]) {
    asm("ldmatrix.sync.aligned.m8n8.x4.shared.b16 {%0,%1,%2,%3}, [%4];"
        : "=r"(r[0]), "=r"(r[1]), "=r"(r[2]), "=r"(r[3]) : "r"(addr) : "memory");
}
static __device__ __forceinline__ void mma16816(float c[4], const uint32_t a[4],
                                                uint32_t b0, uint32_t b1) {
    asm("mma.sync.aligned.m16n8k16.row.col.f32.bf16.bf16.f32 "
        "{%0,%1,%2,%3},{%4,%5,%6,%7},{%8,%9},{%0,%1,%2,%3};"
        : "+f"(c[0]), "+f"(c[1]), "+f"(c[2]), "+f"(c[3])
        : "r"(a[0]), "r"(a[1]), "r"(a[2]), "r"(a[3]), "r"(b0), "r"(b1));
}
static __device__ __forceinline__ void cpa16(uint32_t dst, const void* src) {
    asm volatile("cp.async.cg.shared.global [%0], [%1], 16;"
                 :: "r"(dst), "l"(src) : "memory");
}
static __device__ __forceinline__ void barg(int id) {
    asm volatile("bar.sync %0, 256;" :: "r"(id) : "memory");
}

// ---------------------------------------------------------------------------
// Gather + combine + split: writes bf16 hi/lo rows of
//   A_comb = AFF ? a⊙(cA·h[d]+Σh[s]) + (cA+deg)·c : cA·h[d]+Σh[s]
// Warp per node; rows [N, NPAD) zero-filled.
// ---------------------------------------------------------------------------
template <int AFF>
__global__ void __launch_bounds__(256) k_gather(const float* __restrict__ h,
                                                const float* __restrict__ epsp) {
    int d = (blockIdx.x * blockDim.x + threadIdx.x) >> 5;
    int lane = threadIdx.x & 31;
    if (d >= NPAD) return;
    float4 acc = make_float4(0.f, 0.f, 0.f, 0.f);
    if (d < N_NODES) {
        float cA = 1.0f + *epsp;
        float4 xv = reinterpret_cast<const float4*>(h + (size_t)d * D)[lane];
        acc.x = cA * xv.x; acc.y = cA * xv.y;
        acc.z = cA * xv.z; acc.w = cA * xv.w;
        int beg = g_off[d], end = g_off[d + 1];
        for (int i = beg; i < end; i++) {
            int s = g_elist[i];
            float4 v = reinterpret_cast<const float4*>(h + (size_t)s * D)[lane];
            acc.x += v.x; acc.y += v.y; acc.z += v.z; acc.w += v.w;
        }
        if (AFF) {
            float f = cA + (float)(end - beg);
            float4 a = *reinterpret_cast<const float4*>(g_bn + lane * 4);
            float4 c = *reinterpret_cast<const float4*>(g_bn + D + lane * 4);
            acc.x = a.x * acc.x + f * c.x;
            acc.y = a.y * acc.y + f * c.y;
            acc.z = a.z * acc.z + f * c.z;
            acc.w = a.w * acc.w + f * c.w;
        }
    }
    uint32_t h0, l0, h1, l1;
    split2(acc.x, acc.y, h0, l0);
    split2(acc.z, acc.w, h1, l1);
    size_t base = (size_t)d * D + lane * 4;
    *reinterpret_cast<uint2*>(g_ahi + base) = make_uint2(h0, h1);
    *reinterpret_cast<uint2*>(g_alo + base) = make_uint2(l0, l1);
}

// ---------------------------------------------------------------------------
static __device__ __forceinline__ void mma_3pass(float acc[2][4][4],
                                                 uint32_t Ahi, uint32_t Alo,
                                                 uint32_t Bhi, uint32_t Blo,
                                                 const uint32_t aoff[2],
                                                 const uint32_t boff[2]) {
#pragma unroll
    for (int ks = 0; ks < 8; ks++) {
        uint32_t kb = ks * 32;
        uint32_t ah[2][4], al[2][4], bh[2][4], bl[2][4];
#pragma unroll
        for (int mt = 0; mt < 2; mt++) {
            ldmx4(Ahi + aoff[mt] + kb, ah[mt]);
            ldmx4(Alo + aoff[mt] + kb, al[mt]);
        }
#pragma unroll
        for (int np = 0; np < 2; np++) {
            ldmx4(Bhi + boff[np] + kb, bh[np]);
            ldmx4(Blo + boff[np] + kb, bl[np]);
        }
#pragma unroll
        for (int mt = 0; mt < 2; mt++)
#pragma unroll
            for (int nt = 0; nt < 4; nt++) {
                int np = nt >> 1, o = (nt & 1) * 2;
                mma16816(acc[mt][nt], ah[mt], bh[np][o], bh[np][o + 1]);
            }
#pragma unroll
        for (int mt = 0; mt < 2; mt++)
#pragma unroll
            for (int nt = 0; nt < 4; nt++) {
                int np = nt >> 1, o = (nt & 1) * 2;
                mma16816(acc[mt][nt], ah[mt], bl[np][o], bl[np][o + 1]);
            }
#pragma unroll
        for (int mt = 0; mt < 2; mt++)
#pragma unroll
            for (int nt = 0; nt < 4; nt++) {
                int np = nt >> 1, o = (nt & 1) * 2;
                mma16816(acc[mt][nt], al[mt], bh[np][o], bh[np][o + 1]);
            }
    }
}

static __device__ __forceinline__ void stage_W(const __nv_bfloat16* __restrict__ w,
                                               uint32_t dbase, int t) {
#pragma unroll
    for (int it = 0; it < 4; it++) {
        int c = t + it * 512;
        int row = c >> 4, j = c & 15;
        cpa16(dbase + row * 272 + j * 16, w + row * D + j * 8);
    }
}

static __device__ __forceinline__ void prefetch_A(const float* __restrict__ A,
                                                  int gr, int sq, float4 px[8]) {
    if (gr < N_NODES) {
        const float4* Ar = reinterpret_cast<const float4*>(A + (size_t)gr * D);
#pragma unroll
        for (int j = 0; j < 8; j++) px[j] = Ar[sq * 8 + j];
    }
}

// ---------------------------------------------------------------------------
// Persistent fused GIN MLP: A pre-staged as bf16 hi/lo in global; the stage
// phase is pure cp.async. Dual 256-thread ping-pong groups.
// ---------------------------------------------------------------------------
__global__ void __launch_bounds__(512) k_mlp(const float* __restrict__ b1,
                                             const float* __restrict__ b2,
                                             const __nv_bfloat16* __restrict__ w1h,
                                             const __nv_bfloat16* __restrict__ w1l,
                                             const __nv_bfloat16* __restrict__ w2h,
                                             const __nv_bfloat16* __restrict__ w2l,
                                             float* __restrict__ out) {
    extern __shared__ uint32_t smem[];
    __shared__ float sb1[D], sb2[D], s_sum[D], s_sq[D];

    const int t = threadIdx.x;
    const int grp = t >> 8;
    const int t2 = t & 255;
    const int warp8 = t2 >> 5, lane = t & 31;
    const int wm = warp8 & 1, wn = warp8 >> 1;

    uint32_t* As_hi = smem + grp * 2 * HARR_U32;
    uint32_t* As_lo = As_hi + HARR_U32;
    uint32_t* wbase = smem + 4 * HARR_U32;

    if (t < D) {
        sb1[t] = __ldg(b1 + t);
        sb2[t] = __ldg(b2 + t);
        s_sum[t] = 0.f;
        s_sq[t] = 0.f;
    }

    const uint32_t W1h = smem_u32(wbase);
    const uint32_t W1l = smem_u32(wbase + WARR_U32 * 1);
    const uint32_t W2h = smem_u32(wbase + WARR_U32 * 2);
    const uint32_t W2l = smem_u32(wbase + WARR_U32 * 3);
    stage_W(w1h, W1h, t);
    stage_W(w1l, W1l, t);
    stage_W(w2h, W2h, t);
    stage_W(w2l, W2l, t);
    asm volatile("cp.async.commit_group;" ::: "memory");
    asm volatile("cp.async.wait_group 0;" ::: "memory");
    __syncthreads();

    uint32_t aoff[2], boff[2];
#pragma unroll
    for (int mt = 0; mt < 2; mt++) {
        int row = wm * 32 + mt * 16 + ((lane >> 3) & 1) * 8 + (lane & 7);
        aoff[mt] = row * 272 + (lane >> 4) * 16;
    }
#pragma unroll
    for (int np = 0; np < 2; np++) {
        int row = wn * 32 + np * 16 + (lane >> 4) * 8 + (lane & 7);
        boff[np] = row * 272 + ((lane >> 3) & 1) * 16;
    }
    const uint32_t Ahi = smem_u32(As_hi), Alo = smem_u32(As_lo);
    const int lg = lane >> 2;
    const int c2 = (lane & 3) * 2;
    const int bid = 1 + grp;

    int tile = blockIdx.x * 2 + grp;
    const int step = gridDim.x * 2;

    for (; tile < NT64; tile += step) {
        const int row0 = tile * 64;

        // stage A: pure cp.async from pre-split global tiles
        {
            const __nv_bfloat16* shi = g_ahi + (size_t)row0 * D;
            const __nv_bfloat16* slo = g_alo + (size_t)row0 * D;
#pragma unroll
            for (int it = 0; it < 4; it++) {
                int c = t2 + it * 256;          // 0..1023
                int row = c >> 4, j = c & 15;
                cpa16(Ahi + row * 272 + j * 16, shi + row * D + j * 8);
                cpa16(Alo + row * 272 + j * 16, slo + row * D + j * 8);
            }
            asm volatile("cp.async.commit_group;" ::: "memory");
            asm volatile("cp.async.wait_group 0;" ::: "memory");
        }
        barg(bid);

        float acc[2][4][4];
#pragma unroll
        for (int mt = 0; mt < 2; mt++)
#pragma unroll
            for (int nt = 0; nt < 4; nt++)
#pragma unroll
                for (int i = 0; i < 4; i++) acc[mt][nt][i] = 0.f;

        // ---- GEMM1 ----
        mma_3pass(acc, Ahi, Alo, W1h, W1l, aoff, boff);
        barg(bid);   // GEMM1 reads of As done

        // epilogue1: P = relu(acc+b1) -> bf16 hi/lo back into As
#pragma unroll
        for (int mt = 0; mt < 2; mt++) {
            int ra = wm * 32 + mt * 16 + lg;
            int rb = ra + 8;
#pragma unroll
            for (int nt = 0; nt < 4; nt++) {
                int col = wn * 32 + nt * 8 + c2;
                int o = col >> 1;
                float t0 = fmaxf(acc[mt][nt][0] + sb1[col], 0.f);
                float t1 = fmaxf(acc[mt][nt][1] + sb1[col + 1], 0.f);
                float t2v = fmaxf(acc[mt][nt][2] + sb1[col], 0.f);
                float t3 = fmaxf(acc[mt][nt][3] + sb1[col + 1], 0.f);
                uint32_t hi, lo;
                split2(t0, t1, hi, lo);
                As_hi[ra * HROW_U32 + o] = hi;
                As_lo[ra * HROW_U32 + o] = lo;
                split2(t2v, t3, hi, lo);
                As_hi[rb * HROW_U32 + o] = hi;
                As_lo[rb * HROW_U32 + o] = lo;
#pragma unroll
                for (int i = 0; i < 4; i++) acc[mt][nt][i] = 0.f;
            }
        }
        barg(bid);   // P staged

        // ---- GEMM2 ----
        mma_3pass(acc, Ahi, Alo, W2h, W2l, aoff, boff);
        barg(bid);   // GEMM2 reads done -> next cp.async may overwrite As

        // epilogue2: relu+bias, store out, accumulate column stats
        {
            float sp[4][2], qp[4][2];
#pragma unroll
            for (int nt = 0; nt < 4; nt++) {
                sp[nt][0] = sp[nt][1] = 0.f;
                qp[nt][0] = qp[nt][1] = 0.f;
            }
#pragma unroll
            for (int mt = 0; mt < 2; mt++) {
                int ra = row0 + wm * 32 + mt * 16 + lg;
                int rb = ra + 8;
#pragma unroll
                for (int nt = 0; nt < 4; nt++) {
                    int col = wn * 32 + nt * 8 + c2;
                    float v0 = fmaxf(acc[mt][nt][0] + sb2[col], 0.f);
                    float v1 = fmaxf(acc[mt][nt][1] + sb2[col + 1], 0.f);
                    float v2 = fmaxf(acc[mt][nt][2] + sb2[col], 0.f);
                    float v3 = fmaxf(acc[mt][nt][3] + sb2[col + 1], 0.f);
                    if (ra < N_NODES) {
                        *reinterpret_cast<float2*>(out + (size_t)ra * D + col) =
                            make_float2(v0, v1);
                        sp[nt][0] += v0; sp[nt][1] += v1;
                        qp[nt][0] += v0 * v0; qp[nt][1] += v1 * v1;
                    }
                    if (rb < N_NODES) {
                        *reinterpret_cast<float2*>(out + (size_t)rb * D + col) =
                            make_float2(v2, v3);
                        sp[nt][0] += v2; sp[nt][1] += v3;
                        qp[nt][0] += v2 * v2; qp[nt][1] += v3 * v3;
                    }
                }
            }
#pragma unroll
            for (int nt = 0; nt < 4; nt++) {
#pragma unroll
                for (int d = 4; d < 32; d <<= 1) {
                    sp[nt][0] += __shfl_xor_sync(0xffffffffu, sp[nt][0], d);
                    sp[nt][1] += __shfl_xor_sync(0xffffffffu, sp[nt][1], d);
                    qp[nt][0] += __shfl_xor_sync(0xffffffffu, qp[nt][0], d);
                    qp[nt][1] += __shfl_xor_sync(0xffffffffu, qp[nt][1], d);
                }
            }
            if (lg == 0) {
#pragma unroll
                for (int nt = 0; nt < 4; nt++) {
                    int col = wn * 32 + nt * 8 + c2;
                    atomicAdd(&s_sum[col], sp[nt][0]);
                    atomicAdd(&s_sum[col + 1], sp[nt][1]);
                    atomicAdd(&s_sq[col], qp[nt][0]);
                    atomicAdd(&s_sq[col + 1], qp[nt][1]);
                }
            }
        }
    }

    __syncthreads();
    if (t < D) {
        asm volatile("red.global.add.f32 [%0], %1;" :: "l"(&g_colsum[t]), "f"(s_sum[t]) : "memory");
        asm volatile("red.global.add.f32 [%0], %1;" :: "l"(&g_colsq[t]), "f"(s_sq[t]) : "memory");
    }
}

// ---------------------------------------------------------------------------
// Persistent final linear, dual-group: out = relu((a*A+c) @ Wl^T + bl)
// ---------------------------------------------------------------------------
__global__ void __launch_bounds__(512) k_gemm_l(const float* __restrict__ A,
                                                const float* __restrict__ bias,
                                                const __nv_bfloat16* __restrict__ wh,
                                                const __nv_bfloat16* __restrict__ wl,
                                                float* __restrict__ out) {
    extern __shared__ uint32_t smem[];
    __shared__ float sb[D];

    const int t = threadIdx.x;
    const int grp = t >> 8;
    const int t2 = t & 255;
    const int warp8 = t2 >> 5, lane = t & 31;
    const int wm = warp8 & 1, wn = warp8 >> 1;

    uint32_t* As_hi = smem + grp * 2 * HARR_U32;
    uint32_t* As_lo = As_hi + HARR_U32;
    uint32_t* wbase = smem + 4 * HARR_U32;

    if (t < D) sb[t] = __ldg(bias + t);

    const uint32_t Wh = smem_u32(wbase);
    const uint32_t Wl = smem_u32(wbase + WARR_U32);
    stage_W(wh, Wh, t);
    stage_W(wl, Wl, t);
    asm volatile("cp.async.commit_group;" ::: "memory");

    uint32_t aoff[2], boff[2];
#pragma unroll
    for (int mt = 0; mt < 2; mt++) {
        int row = wm * 32 + mt * 16 + ((lane >> 3) & 1) * 8 + (lane & 7);
        aoff[mt] = row * 272 + (lane >> 4) * 16;
    }
#pragma unroll
    for (int np = 0; np < 2; np++) {
        int row = wn * 32 + np * 16 + (lane >> 4) * 8 + (lane & 7);
        boff[np] = row * 272 + ((lane >> 3) & 1) * 16;
    }
    const uint32_t Ahi = smem_u32(As_hi), Alo = smem_u32(As_lo);
    const int lg = lane >> 2;
    const int c2 = (lane & 3) * 2;
    const int srow = t2 >> 2, sq = t2 & 3;
    const int bid = 1 + grp;

    int tile = blockIdx.x * 2 + grp;
    const int step = gridDim.x * 2;
    float4 px[8];
    prefetch_A(A, tile * 64 + srow, sq, px);
    asm volatile("cp.async.wait_group 0;" ::: "memory");
    __syncthreads();

    for (; tile < NT64; tile += step) {
        const int row0 = tile * 64;
        const int gr = row0 + srow;

#pragma unroll
        for (int j = 0; j < 8; j++) {
            int f4 = sq * 8 + j;
            float4 v = make_float4(0.f, 0.f, 0.f, 0.f);
            if (gr < N_NODES) {
                v = px[j];
                float4 a = *reinterpret_cast<const float4*>(g_bn + f4 * 4);
                float4 c = *reinterpret_cast<const float4*>(g_bn + D + f4 * 4);
                v.x = a.x * v.x + c.x; v.y = a.y * v.y + c.y;
                v.z = a.z * v.z + c.z; v.w = a.w * v.w + c.w;
            }
            uint32_t h0, l0, h1, l1;
            split2(v.x, v.y, h0, l0);
            split2(v.z, v.w, h1, l1);
            int o = srow * HROW_U32 + f4 * 2;
            *reinterpret_cast<uint2*>(&As_hi[o]) = make_uint2(h0, h1);
            *reinterpret_cast<uint2*>(&As_lo[o]) = make_uint2(l0, l1);
        }
        barg(bid);

        float acc[2][4][4];
#pragma unroll
        for (int mt = 0; mt < 2; mt++)
#pragma unroll
            for (int nt = 0; nt < 4; nt++)
#pragma unroll
                for (int i = 0; i < 4; i++) acc[mt][nt][i] = 0.f;

        mma_3pass(acc, Ahi, Alo, Wh, Wl, aoff, boff);

        const int ntile = tile + step;
        if (ntile < NT64) prefetch_A(A, ntile * 64 + srow, sq, px);

        barg(bid);

#pragma unroll
        for (int mt = 0; mt < 2; mt++) {
            int ra = row0 + wm * 32 + mt * 16 + lg;
            int rb = ra + 8;
#pragma unroll
            for (int nt = 0; nt < 4; nt++) {
                int col = wn * 32 + nt * 8 + c2;
                if (ra < N_NODES)
                    *reinterpret_cast<float2*>(out + (size_t)ra * D + col) =
                        make_float2(fmaxf(acc[mt][nt][0] + sb[col], 0.f),
                                    fmaxf(acc[mt][nt][1] + sb[col + 1], 0.f));
                if (rb < N_NODES)
                    *reinterpret_cast<float2*>(out + (size_t)rb * D + col) =
                        make_float2(fmaxf(acc[mt][nt][2] + sb[col], 0.f),
                                    fmaxf(acc[mt][nt][3] + sb[col + 1], 0.f));
            }
        }
    }
}

// ---------------------------------------------------------------------------
__global__ void k_bnprep(const float* __restrict__ gamma,
                         const float* __restrict__ beta) {
    int t = threadIdx.x;
    float inv_n = 1.0f / (float)N_NODES;
    float mu = g_colsum[t] * inv_n;
    float var = g_colsq[t] * inv_n - mu * mu;
    float a = gamma[t] * rsqrtf(var + 1e-5f);
    g_bn[t] = a;
    g_bn[D + t] = beta[t] - mu * a;
    g_colsum[t] = 0.f;
    g_colsq[t] = 0.f;
}

// ---------------------------------------------------------------------------
__global__ void __launch_bounds__(256) k_pairs(const float* __restrict__ h,
                                               const int* __restrict__ pairs,
                                               const float* __restrict__ Wfc,
                                               const float* __restrict__ bfc,
                                               float* __restrict__ out) {
    __shared__ float sW[O_OUT][D];
    __shared__ float sb[O_OUT];
    int t = threadIdx.x;
    for (int i = t; i < O_OUT * D; i += 256) sW[i / D][i % D] = Wfc[i];
    if (t < O_OUT) sb[t] = bfc[t];
    __syncthreads();

    int p = (blockIdx.x * 256 + t) >> 5;
    int lane = t & 31;
    if (p >= P_PAIRS) return;

    int i0 = pairs[2 * p];
    int i1 = pairs[2 * p + 1];
    float4 u = reinterpret_cast<const float4*>(h + (size_t)i0 * D)[lane];
    float4 v = reinterpret_cast<const float4*>(h + (size_t)i1 * D)[lane];
    float4 w = make_float4(u.x * v.x, u.y * v.y, u.z * v.z, u.w * v.w);

    float s[O_OUT];
#pragma unroll
    for (int o = 0; o < O_OUT; o++)
        s[o] = w.x * sW[o][4 * lane + 0] + w.y * sW[o][4 * lane + 1] +
               w.z * sW[o][4 * lane + 2] + w.w * sW[o][4 * lane + 3];
#pragma unroll
    for (int o = 0; o < O_OUT; o++)
#pragma unroll
        for (int off = 16; off > 0; off >>= 1)
            s[o] += __shfl_xor_sync(0xffffffffu, s[o], off);
    if (lane == 0)
#pragma unroll
        for (int o = 0; o < O_OUT; o++) out[(size_t)p * O_OUT + o] = s[o] + sb[o];
}

// ---------------------------------------------------------------------------
extern "C" void kernel_launch(void* const* d_in, const int* in_sizes, int n_in,
                              void* d_out, int out_size) {
    const float* x    = (const float*)d_in[0];
    const float* W1a  = (const float*)d_in[1];
    const float* b1a  = (const float*)d_in[2];
    const float* W2a  = (const float*)d_in[3];
    const float* b2a  = (const float*)d_in[4];
    const float* g0   = (const float*)d_in[5];
    const float* bt0  = (const float*)d_in[6];
    const float* eps0 = (const float*)d_in[7];
    const float* W1b  = (const float*)d_in[8];
    const float* b1b  = (const float*)d_in[9];
    const float* W2b  = (const float*)d_in[10];
    const float* b2b  = (const float*)d_in[11];
    const float* g1   = (const float*)d_in[12];
    const float* bt1  = (const float*)d_in[13];
    const float* eps1 = (const float*)d_in[14];
    const float* Wl   = (const float*)d_in[15];
    const float* bl   = (const float*)d_in[16];
    const float* Wfc  = (const float*)d_in[17];
    const float* bfc  = (const float*)d_in[18];
    const int* esrc   = (const int*)d_in[19];
    const int* edst   = (const int*)d_in[20];
    const int* pairs  = (const int*)d_in[21];
    float* out = (float*)d_out;

    float *t, *h;
    __nv_bfloat16 *wh, *wl;
    cudaGetSymbolAddress((void**)&t, g_t);
    cudaGetSymbolAddress((void**)&h, g_h);
    cudaGetSymbolAddress((void**)&wh, g_wh);
    cudaGetSymbolAddress((void**)&wl, g_wl);

    cudaFuncSetAttribute(k_mlp, cudaFuncAttributeMaxDynamicSharedMemorySize, SMEM_MLP);
    cudaFuncSetAttribute(k_gemm_l, cudaFuncAttributeMaxDynamicSharedMemorySize, SMEM_GL);

    const int EB = (E_EDGES + 255) / 256;
    const int GBg = (NPAD * 32 + 255) / 256;     // gather: warp per padded node
    const int PB = (P_PAIRS * 32) / 256;
    const int WS = D * D;
    const int PG = 148;

    // prep + CSR build
    k_prep_w<<<(5 * WS + 255) / 256, 256>>>(W1a, W2a, W1b, W2b, Wl);
    k_hist<<<EB, 256>>>(edst);
    k_scan<<<1, 1024>>>();
    k_fill<<<EB, 256>>>(esrc, edst);

    // Layer A: gather+combine+split(x) -> g_ahi/lo; MLP -> h
    k_gather<0><<<GBg, 256>>>(x, eps0);
    k_mlp<<<PG, 512, SMEM_MLP>>>(b1a, b2a,
                                 wh + 0 * WS, wl + 0 * WS,
                                 wh + 1 * WS, wl + 1 * WS, h);
    k_bnprep<<<1, 128>>>(g0, bt0);

    // Layer B: gather+BN0-affine+combine+split(h) -> g_ahi/lo; MLP -> t
    k_gather<1><<<GBg, 256>>>(h, eps1);
    k_mlp<<<PG, 512, SMEM_MLP>>>(b1b, b2b,
                                 wh + 2 * WS, wl + 2 * WS,
                                 wh + 3 * WS, wl + 3 * WS, t);
    k_bnprep<<<1, 128>>>(g1, bt1);

    // Final linear (BN1 affine folded): t -> h; pair head reads h
    k_gemm_l<<<PG, 512, SMEM_GL>>>(t, bl, wh + 4 * WS, wl + 4 * WS, h);
    k_pairs<<<PB, 256>>>(h, pairs, Wfc, bfc, out);
}

// round 16
// speedup vs baseline: 1.5748x; 1.0477x over previous
#include <cuda_runtime.h>
#include <cuda_bf16.h>
#include <cstdint>

#define N_NODES 50000
#define E_EDGES 600000
#define D 128
#define P_PAIRS 131072
#define O_OUT 7
#define NT64 782                             // ceil(N/64)
#define NPAD (NT64 * 64)                     // 50048

#define HROW_U32 68
#define HARR_U32 (64 * HROW_U32)
#define HARR_BYTES (HARR_U32 * 4)
#define WARR_U32 (128 * HROW_U32)
#define WARR_BYTES (WARR_U32 * 4)
#define SMEM_MLP (4 * HARR_BYTES + 4 * WARR_BYTES)
#define SMEM_GL  (4 * HARR_BYTES + 2 * WARR_BYTES)

// Scratch
__device__ float g_h[N_NODES * D];
__device__ float g_colsum[D];
__device__ float g_colsq[D];
__device__ float g_bn[2 * D];
__device__ float g_bl2[D];                   // folded final bias: Wl@c + bl
__device__ __nv_bfloat16 g_wh[5 * D * D];    // W1a,W2a,W1b,W2b,[Wl*a] (hi)
__device__ __nv_bfloat16 g_wl[5 * D * D];    // (lo)
__device__ __nv_bfloat16 g_ahi[NPAD * D];    // pre-split MLP input (hi)
__device__ __nv_bfloat16 g_alo[NPAD * D];    // (lo)
// CSR (rebuilt every launch)
__device__ int g_deg[N_NODES];
__device__ int g_off[N_NODES + 1];
__device__ int g_cur[N_NODES];
__device__ int g_elist[E_EDGES];

// ---------------------------------------------------------------------------
__global__ void k_prep_w(const float* __restrict__ w0, const float* __restrict__ w1,
                         const float* __restrict__ w2, const float* __restrict__ w3) {
    int i = blockIdx.x * blockDim.x + threadIdx.x;
    if (i < N_NODES) g_deg[i] = 0;
    if (i < D) { g_colsum[i] = 0.f; g_colsq[i] = 0.f; }
    if (i >= 4 * D * D) return;
    const float* srcs[4] = {w0, w1, w2, w3};
    float v = srcs[i >> 14][i & 16383];
    __nv_bfloat16 h = __float2bfloat16(v);
    g_wh[i] = h;
    g_wl[i] = __float2bfloat16(v - __bfloat162float(h));
}

__global__ void k_hist(const int* __restrict__ dst) {
    int e = blockIdx.x * blockDim.x + threadIdx.x;
    if (e < E_EDGES) atomicAdd(&g_deg[dst[e]], 1);
}

__global__ void __launch_bounds__(1024) k_scan() {
    __shared__ int s_tot[1024];
    const int CH = (N_NODES + 1023) / 1024;
    int t = threadIdx.x;
    int base = t * CH;
    int sum = 0;
    for (int i = 0; i < CH; i++) {
        int idx = base + i;
        if (idx < N_NODES) sum += g_deg[idx];
    }
    s_tot[t] = sum;
    __syncthreads();
    for (int off = 1; off < 1024; off <<= 1) {
        int v = 0;
        if (t >= off) v = s_tot[t - off];
        __syncthreads();
        if (t >= off) s_tot[t] += v;
        __syncthreads();
    }
    int run = (t == 0) ? 0 : s_tot[t - 1];
    for (int i = 0; i < CH; i++) {
        int idx = base + i;
        if (idx < N_NODES) {
            g_off[idx] = run;
            g_cur[idx] = run;
            run += g_deg[idx];
        }
    }
    if (t == 1023) g_off[N_NODES] = s_tot[1023];
}

__global__ void k_fill(const int* __restrict__ src, const int* __restrict__ dst) {
    int e = blockIdx.x * blockDim.x + threadIdx.x;
    if (e >= E_EDGES) return;
    int pos = atomicAdd(&g_cur[dst[e]], 1);
    g_elist[pos] = src[e];
}

// ---------------------------------------------------------------------------
static __device__ __forceinline__ uint32_t smem_u32(const void* p) {
    return (uint32_t)__cvta_generic_to_shared(p);
}
static __device__ __forceinline__ void split2(float a, float b, uint32_t& hi, uint32_t& lo) {
    __nv_bfloat162 h = __floats2bfloat162_rn(a, b);
    float ra = a - __bfloat162float(h.x);
    float rb = b - __bfloat162float(h.y);
    __nv_bfloat162 l = __floats2bfloat162_rn(ra, rb);
    hi = *reinterpret_cast<uint32_t*>(&h);
    lo = *reinterpret_cast<uint32_t*>(&l);
}
static __device__ __forceinline__ void ldmx4(uint32_t addr, uint32_t r[4]) {
    asm("ldmatrix.sync.aligned.m8n8.x4.shared.b16 {%0,%1,%2,%3}, [%4];"
        : "=r"(r[0]), "=r"(r[1]), "=r"(r[2]), "=r"(r[3]) : "r"(addr) : "memory");
}
static __device__ __forceinline__ void mma16816(float c[4], const uint32_t a[4],
                                                uint32_t b0, uint32_t b1) {
    asm("mma.sync.aligned.m16n8k16.row.col.f32.bf16.bf16.f32 "
        "{%0,%1,%2,%3},{%4,%5,%6,%7},{%8,%9},{%0,%1,%2,%3};"
        : "+f"(c[0]), "+f"(c[1]), "+f"(c[2]), "+f"(c[3])
        : "r"(a[0]), "r"(a[1]), "r"(a[2]), "r"(a[3]), "r"(b0), "r"(b1));
}
static __device__ __forceinline__ void cpa16(uint32_t dst, const void* src) {
    asm volatile("cp.async.cg.shared.global [%0], [%1], 16;"
                 :: "r"(dst), "l"(src) : "memory");
}
static __device__ __forceinline__ void barg(int id) {
    asm volatile("bar.sync %0, 256;" :: "r"(id) : "memory");
}

// ---------------------------------------------------------------------------
// Fold BN1 affine into final weight: Wl' = Wl ⊙ a (per-col), bias' = Wl@c + bl
// Run AFTER the second bnprep. Writes split Wl' into weight slot 4.
// ---------------------------------------------------------------------------
__global__ void k_prep_l(const float* __restrict__ Wl, const float* __restrict__ bl) {
    int i = blockIdx.x * blockDim.x + threadIdx.x;
    // bias': 32 lanes per output j
    if (i < 128 * 32) {
        int j = i >> 5, lane = i & 31;
        const float4* Wr = reinterpret_cast<const float4*>(Wl + j * D);
        float4 w = Wr[lane];
        float4 c = *reinterpret_cast<const float4*>(g_bn + D + lane * 4);
        float s = w.x * c.x + w.y * c.y + w.z * c.z + w.w * c.w;
#pragma unroll
        for (int off = 16; off > 0; off >>= 1)
            s += __shfl_xor_sync(0xffffffffu, s, off);
        if (lane == 0) g_bl2[j] = s + bl[j];
    }
    if (i >= D * D) return;
    int k = i & 127;
    float v = Wl[i] * g_bn[k];
    __nv_bfloat16 h = __float2bfloat16(v);
    g_wh[4 * D * D + i] = h;
    g_wl[4 * D * D + i] = __float2bfloat16(v - __bfloat162float(h));
}

// ---------------------------------------------------------------------------
// Gather + combine + split -> g_ahi/g_alo (bf16 hi/lo). Warp per node.
// A_comb = AFF ? a⊙(cA·h[d]+Σh[s]) + (cA+deg)·c : cA·h[d]+Σh[s]
// ---------------------------------------------------------------------------
template <int AFF>
__global__ void __launch_bounds__(256) k_gather(const float* __restrict__ h,
                                                const float* __restrict__ epsp) {
    int d = (blockIdx.x * blockDim.x + threadIdx.x) >> 5;
    int lane = threadIdx.x & 31;
    if (d >= NPAD) return;
    float4 acc = make_float4(0.f, 0.f, 0.f, 0.f);
    if (d < N_NODES) {
        float cA = 1.0f + *epsp;
        float4 xv = reinterpret_cast<const float4*>(h + (size_t)d * D)[lane];
        acc.x = cA * xv.x; acc.y = cA * xv.y;
        acc.z = cA * xv.z; acc.w = cA * xv.w;
        int beg = g_off[d], end = g_off[d + 1];
        for (int i = beg; i < end; i++) {
            int s = g_elist[i];
            float4 v = reinterpret_cast<const float4*>(h + (size_t)s * D)[lane];
            acc.x += v.x; acc.y += v.y; acc.z += v.z; acc.w += v.w;
        }
        if (AFF) {
            float f = cA + (float)(end - beg);
            float4 a = *reinterpret_cast<const float4*>(g_bn + lane * 4);
            float4 c = *reinterpret_cast<const float4*>(g_bn + D + lane * 4);
            acc.x = a.x * acc.x + f * c.x;
            acc.y = a.y * acc.y + f * c.y;
            acc.z = a.z * acc.z + f * c.z;
            acc.w = a.w * acc.w + f * c.w;
        }
    }
    uint32_t h0, l0, h1, l1;
    split2(acc.x, acc.y, h0, l0);
    split2(acc.z, acc.w, h1, l1);
    size_t base = (size_t)d * D + lane * 4;
    *reinterpret_cast<uint2*>(g_ahi + base) = make_uint2(h0, h1);
    *reinterpret_cast<uint2*>(g_alo + base) = make_uint2(l0, l1);
}

// ---------------------------------------------------------------------------
static __device__ __forceinline__ void mma_3pass(float acc[2][4][4],
                                                 uint32_t Ahi, uint32_t Alo,
                                                 uint32_t Bhi, uint32_t Blo,
                                                 const uint32_t aoff[2],
                                                 const uint32_t boff[2]) {
#pragma unroll
    for (int ks = 0; ks < 8; ks++) {
        uint32_t kb = ks * 32;
        uint32_t ah[2][4], al[2][4], bh[2][4], bl[2][4];
#pragma unroll
        for (int mt = 0; mt < 2; mt++) {
            ldmx4(Ahi + aoff[mt] + kb, ah[mt]);
            ldmx4(Alo + aoff[mt] + kb, al[mt]);
        }
#pragma unroll
        for (int np = 0; np < 2; np++) {
            ldmx4(Bhi + boff[np] + kb, bh[np]);
            ldmx4(Blo + boff[np] + kb, bl[np]);
        }
#pragma unroll
        for (int mt = 0; mt < 2; mt++)
#pragma unroll
            for (int nt = 0; nt < 4; nt++) {
                int np = nt >> 1, o = (nt & 1) * 2;
                mma16816(acc[mt][nt], ah[mt], bh[np][o], bh[np][o + 1]);
            }
#pragma unroll
        for (int mt = 0; mt < 2; mt++)
#pragma unroll
            for (int nt = 0; nt < 4; nt++) {
                int np = nt >> 1, o = (nt & 1) * 2;
                mma16816(acc[mt][nt], ah[mt], bl[np][o], bl[np][o + 1]);
            }
#pragma unroll
        for (int mt = 0; mt < 2; mt++)
#pragma unroll
            for (int nt = 0; nt < 4; nt++) {
                int np = nt >> 1, o = (nt & 1) * 2;
                mma16816(acc[mt][nt], al[mt], bh[np][o], bh[np][o + 1]);
            }
    }
}

static __device__ __forceinline__ void stage_W(const __nv_bfloat16* __restrict__ w,
                                               uint32_t dbase, int t) {
#pragma unroll
    for (int it = 0; it < 4; it++) {
        int c = t + it * 512;
        int row = c >> 4, j = c & 15;
        cpa16(dbase + row * 272 + j * 16, w + row * D + j * 8);
    }
}

// stage one 64-row A tile (hi+lo) via cp.async; t2 in [0,256)
static __device__ __forceinline__ void stage_A_cp(int row0, uint32_t Ahi, uint32_t Alo,
                                                  int t2) {
    const __nv_bfloat16* shi = g_ahi + (size_t)row0 * D;
    const __nv_bfloat16* slo = g_alo + (size_t)row0 * D;
#pragma unroll
    for (int it = 0; it < 4; it++) {
        int c = t2 + it * 256;
        int row = c >> 4, j = c & 15;
        cpa16(Ahi + row * 272 + j * 16, shi + row * D + j * 8);
        cpa16(Alo + row * 272 + j * 16, slo + row * D + j * 8);
    }
    asm volatile("cp.async.commit_group;" ::: "memory");
    asm volatile("cp.async.wait_group 0;" ::: "memory");
}

// ---------------------------------------------------------------------------
// Persistent fused GIN MLP. OUTB16=0: write fp32 out. OUTB16=1: write
// pre-split bf16 (hi/lo) into g_ahi/g_alo (rows >= N zeroed) for k_gemm_l.
// ---------------------------------------------------------------------------
template <int OUTB16>
__global__ void __launch_bounds__(512) k_mlp(const float* __restrict__ b1,
                                             const float* __restrict__ b2,
                                             const __nv_bfloat16* __restrict__ w1h,
                                             const __nv_bfloat16* __restrict__ w1l,
                                             const __nv_bfloat16* __restrict__ w2h,
                                             const __nv_bfloat16* __restrict__ w2l,
                                             float* __restrict__ out) {
    extern __shared__ uint32_t smem[];
    __shared__ float sb1[D], sb2[D], s_sum[D], s_sq[D];

    const int t = threadIdx.x;
    const int grp = t >> 8;
    const int t2 = t & 255;
    const int warp8 = t2 >> 5, lane = t & 31;
    const int wm = warp8 & 1, wn = warp8 >> 1;

    uint32_t* As_hi = smem + grp * 2 * HARR_U32;
    uint32_t* As_lo = As_hi + HARR_U32;
    uint32_t* wbase = smem + 4 * HARR_U32;

    if (t < D) {
        sb1[t] = __ldg(b1 + t);
        sb2[t] = __ldg(b2 + t);
        s_sum[t] = 0.f;
        s_sq[t] = 0.f;
    }

    const uint32_t W1h = smem_u32(wbase);
    const uint32_t W1l = smem_u32(wbase + WARR_U32 * 1);
    const uint32_t W2h = smem_u32(wbase + WARR_U32 * 2);
    const uint32_t W2l = smem_u32(wbase + WARR_U32 * 3);
    stage_W(w1h, W1h, t);
    stage_W(w1l, W1l, t);
    stage_W(w2h, W2h, t);
    stage_W(w2l, W2l, t);
    asm volatile("cp.async.commit_group;" ::: "memory");
    asm volatile("cp.async.wait_group 0;" ::: "memory");
    __syncthreads();

    uint32_t aoff[2], boff[2];
#pragma unroll
    for (int mt = 0; mt < 2; mt++) {
        int row = wm * 32 + mt * 16 + ((lane >> 3) & 1) * 8 + (lane & 7);
        aoff[mt] = row * 272 + (lane >> 4) * 16;
    }
#pragma unroll
    for (int np = 0; np < 2; np++) {
        int row = wn * 32 + np * 16 + (lane >> 4) * 8 + (lane & 7);
        boff[np] = row * 272 + ((lane >> 3) & 1) * 16;
    }
    const uint32_t Ahi = smem_u32(As_hi), Alo = smem_u32(As_lo);
    const int lg = lane >> 2;
    const int c2 = (lane & 3) * 2;
    const int bid = 1 + grp;

    int tile = blockIdx.x * 2 + grp;
    const int step = gridDim.x * 2;

    for (; tile < NT64; tile += step) {
        const int row0 = tile * 64;

        stage_A_cp(row0, Ahi, Alo, t2);
        barg(bid);

        float acc[2][4][4];
#pragma unroll
        for (int mt = 0; mt < 2; mt++)
#pragma unroll
            for (int nt = 0; nt < 4; nt++)
#pragma unroll
                for (int i = 0; i < 4; i++) acc[mt][nt][i] = 0.f;

        // ---- GEMM1 ----
        mma_3pass(acc, Ahi, Alo, W1h, W1l, aoff, boff);
        barg(bid);

        // epilogue1: P = relu(acc+b1) -> bf16 hi/lo back into As
#pragma unroll
        for (int mt = 0; mt < 2; mt++) {
            int ra = wm * 32 + mt * 16 + lg;
            int rb = ra + 8;
#pragma unroll
            for (int nt = 0; nt < 4; nt++) {
                int col = wn * 32 + nt * 8 + c2;
                int o = col >> 1;
                float t0 = fmaxf(acc[mt][nt][0] + sb1[col], 0.f);
                float t1 = fmaxf(acc[mt][nt][1] + sb1[col + 1], 0.f);
                float t2v = fmaxf(acc[mt][nt][2] + sb1[col], 0.f);
                float t3 = fmaxf(acc[mt][nt][3] + sb1[col + 1], 0.f);
                uint32_t hi, lo;
                split2(t0, t1, hi, lo);
                As_hi[ra * HROW_U32 + o] = hi;
                As_lo[ra * HROW_U32 + o] = lo;
                split2(t2v, t3, hi, lo);
                As_hi[rb * HROW_U32 + o] = hi;
                As_lo[rb * HROW_U32 + o] = lo;
#pragma unroll
                for (int i = 0; i < 4; i++) acc[mt][nt][i] = 0.f;
            }
        }
        barg(bid);

        // ---- GEMM2 ----
        mma_3pass(acc, Ahi, Alo, W2h, W2l, aoff, boff);
        barg(bid);

        // epilogue2: relu+bias, store, column stats
        {
            float sp[4][2], qp[4][2];
#pragma unroll
            for (int nt = 0; nt < 4; nt++) {
                sp[nt][0] = sp[nt][1] = 0.f;
                qp[nt][0] = qp[nt][1] = 0.f;
            }
#pragma unroll
            for (int mt = 0; mt < 2; mt++) {
                int ra = row0 + wm * 32 + mt * 16 + lg;
                int rb = ra + 8;
#pragma unroll
                for (int nt = 0; nt < 4; nt++) {
                    int col = wn * 32 + nt * 8 + c2;
                    float v0 = fmaxf(acc[mt][nt][0] + sb2[col], 0.f);
                    float v1 = fmaxf(acc[mt][nt][1] + sb2[col + 1], 0.f);
                    float v2 = fmaxf(acc[mt][nt][2] + sb2[col], 0.f);
                    float v3 = fmaxf(acc[mt][nt][3] + sb2[col + 1], 0.f);
                    if (OUTB16) {
                        uint32_t hi = 0, lo = 0;
                        if (ra < N_NODES) {
                            split2(v0, v1, hi, lo);
                            sp[nt][0] += v0; sp[nt][1] += v1;
                            qp[nt][0] += v0 * v0; qp[nt][1] += v1 * v1;
                        }
                        *reinterpret_cast<uint32_t*>(g_ahi + (size_t)ra * D + col) = hi;
                        *reinterpret_cast<uint32_t*>(g_alo + (size_t)ra * D + col) = lo;
                        hi = lo = 0;
                        if (rb < N_NODES) {
                            split2(v2, v3, hi, lo);
                            sp[nt][0] += v2; sp[nt][1] += v3;
                            qp[nt][0] += v2 * v2; qp[nt][1] += v3 * v3;
                        }
                        *reinterpret_cast<uint32_t*>(g_ahi + (size_t)rb * D + col) = hi;
                        *reinterpret_cast<uint32_t*>(g_alo + (size_t)rb * D + col) = lo;
                    } else {
                        if (ra < N_NODES) {
                            *reinterpret_cast<float2*>(out + (size_t)ra * D + col) =
                                make_float2(v0, v1);
                            sp[nt][0] += v0; sp[nt][1] += v1;
                            qp[nt][0] += v0 * v0; qp[nt][1] += v1 * v1;
                        }
                        if (rb < N_NODES) {
                            *reinterpret_cast<float2*>(out + (size_t)rb * D + col) =
                                make_float2(v2, v3);
                            sp[nt][0] += v2; sp[nt][1] += v3;
                            qp[nt][0] += v2 * v2; qp[nt][1] += v3 * v3;
                        }
                    }
                }
            }
#pragma unroll
            for (int nt = 0; nt < 4; nt++) {
#pragma unroll
                for (int d = 4; d < 32; d <<= 1) {
                    sp[nt][0] += __shfl_xor_sync(0xffffffffu, sp[nt][0], d);
                    sp[nt][1] += __shfl_xor_sync(0xffffffffu, sp[nt][1], d);
                    qp[nt][0] += __shfl_xor_sync(0xffffffffu, qp[nt][0], d);
                    qp[nt][1] += __shfl_xor_sync(0xffffffffu, qp[nt][1], d);
                }
            }
            if (lg == 0) {
#pragma unroll
                for (int nt = 0; nt < 4; nt++) {
                    int col = wn * 32 + nt * 8 + c2;
                    atomicAdd(&s_sum[col], sp[nt][0]);
                    atomicAdd(&s_sum[col + 1], sp[nt][1]);
                    atomicAdd(&s_sq[col], qp[nt][0]);
                    atomicAdd(&s_sq[col + 1], qp[nt][1]);
                }
            }
        }
    }

    __syncthreads();
    if (t < D) {
        asm volatile("red.global.add.f32 [%0], %1;" :: "l"(&g_colsum[t]), "f"(s_sum[t]) : "memory");
        asm volatile("red.global.add.f32 [%0], %1;" :: "l"(&g_colsq[t]), "f"(s_sq[t]) : "memory");
    }
}

// ---------------------------------------------------------------------------
// Final linear: out = relu(A@Wl'^T + bias'). A pre-split in g_ahi/g_alo.
// ---------------------------------------------------------------------------
__global__ void __launch_bounds__(512) k_gemm_l(const __nv_bfloat16* __restrict__ wh,
                                                const __nv_bfloat16* __restrict__ wl,
                                                float* __restrict__ out) {
    extern __shared__ uint32_t smem[];
    __shared__ float sb[D];

    const int t = threadIdx.x;
    const int grp = t >> 8;
    const int t2 = t & 255;
    const int warp8 = t2 >> 5, lane = t & 31;
    const int wm = warp8 & 1, wn = warp8 >> 1;

    uint32_t* As_hi = smem + grp * 2 * HARR_U32;
    uint32_t* As_lo = As_hi + HARR_U32;
    uint32_t* wbase = smem + 4 * HARR_U32;

    if (t < D) sb[t] = g_bl2[t];

    const uint32_t Wh = smem_u32(wbase);
    const uint32_t Wl = smem_u32(wbase + WARR_U32);
    stage_W(wh, Wh, t);
    stage_W(wl, Wl, t);
    asm volatile("cp.async.commit_group;" ::: "memory");
    asm volatile("cp.async.wait_group 0;" ::: "memory");
    __syncthreads();

    uint32_t aoff[2], boff[2];
#pragma unroll
    for (int mt = 0; mt < 2; mt++) {
        int row = wm * 32 + mt * 16 + ((lane >> 3) & 1) * 8 + (lane & 7);
        aoff[mt] = row * 272 + (lane >> 4) * 16;
    }
#pragma unroll
    for (int np = 0; np < 2; np++) {
        int row = wn * 32 + np * 16 + (lane >> 4) * 8 + (lane & 7);
        boff[np] = row * 272 + ((lane >> 3) & 1) * 16;
    }
    const uint32_t Ahi = smem_u32(As_hi), Alo = smem_u32(As_lo);
    const int lg = lane >> 2;
    const int c2 = (lane & 3) * 2;
    const int bid = 1 + grp;

    int tile = blockIdx.x * 2 + grp;
    const int step = gridDim.x * 2;

    for (; tile < NT64; tile += step) {
        const int row0 = tile * 64;

        stage_A_cp(row0, Ahi, Alo, t2);
        barg(bid);

        float acc[2][4][4];
#pragma unroll
        for (int mt = 0; mt < 2; mt++)
#pragma unroll
            for (int nt = 0; nt < 4; nt++)
#pragma unroll
                for (int i = 0; i < 4; i++) acc[mt][nt][i] = 0.f;

        mma_3pass(acc, Ahi, Alo, Wh, Wl, aoff, boff);
        barg(bid);

#pragma unroll
        for (int mt = 0; mt < 2; mt++) {
            int ra = row0 + wm * 32 + mt * 16 + lg;
            int rb = ra + 8;
#pragma unroll
            for (int nt = 0; nt < 4; nt++) {
                int col = wn * 32 + nt * 8 + c2;
                if (ra < N_NODES)
                    *reinterpret_cast<float2*>(out + (size_t)ra * D + col) =
                        make_float2(fmaxf(acc[mt][nt][0] + sb[col], 0.f),
                                    fmaxf(acc[mt][nt][1] + sb[col + 1], 0.f));
                if (rb < N_NODES)
                    *reinterpret_cast<float2*>(out + (size_t)rb * D + col) =
                        make_float2(fmaxf(acc[mt][nt][2] + sb[col], 0.f),
                                    fmaxf(acc[mt][nt][3] + sb[col + 1], 0.f));
            }
        }
    }
}

// ---------------------------------------------------------------------------
__global__ void k_bnprep(const float* __restrict__ gamma,
                         const float* __restrict__ beta) {
    int t = threadIdx.x;
    float inv_n = 1.0f / (float)N_NODES;
    float mu = g_colsum[t] * inv_n;
    float var = g_colsq[t] * inv_n - mu * mu;
    float a = gamma[t] * rsqrtf(var + 1e-5f);
    g_bn[t] = a;
    g_bn[D + t] = beta[t] - mu * a;
    g_colsum[t] = 0.f;
    g_colsq[t] = 0.f;
}

// ---------------------------------------------------------------------------
// Pair head: 2 pairs per warp (4 independent row loads in flight)
// ---------------------------------------------------------------------------
__global__ void __launch_bounds__(256) k_pairs(const float* __restrict__ h,
                                               const int* __restrict__ pairs,
                                               const float* __restrict__ Wfc,
                                               const float* __restrict__ bfc,
                                               float* __restrict__ out) {
    __shared__ float sW[O_OUT][D];
    __shared__ float sb[O_OUT];
    int t = threadIdx.x;
    for (int i = t; i < O_OUT * D; i += 256) sW[i / D][i % D] = Wfc[i];
    if (t < O_OUT) sb[t] = bfc[t];
    __syncthreads();

    int w = (blockIdx.x * 256 + t) >> 5;
    int lane = t & 31;
    int p0 = w * 2;
    if (p0 >= P_PAIRS) return;

    int ia0 = pairs[2 * p0];
    int ib0 = pairs[2 * p0 + 1];
    int ia1 = pairs[2 * p0 + 2];
    int ib1 = pairs[2 * p0 + 3];
    float4 u0 = reinterpret_cast<const float4*>(h + (size_t)ia0 * D)[lane];
    float4 v0 = reinterpret_cast<const float4*>(h + (size_t)ib0 * D)[lane];
    float4 u1 = reinterpret_cast<const float4*>(h + (size_t)ia1 * D)[lane];
    float4 v1 = reinterpret_cast<const float4*>(h + (size_t)ib1 * D)[lane];
    float4 w0 = make_float4(u0.x * v0.x, u0.y * v0.y, u0.z * v0.z, u0.w * v0.w);
    float4 w1 = make_float4(u1.x * v1.x, u1.y * v1.y, u1.z * v1.z, u1.w * v1.w);

    float s0[O_OUT], s1[O_OUT];
#pragma unroll
    for (int o = 0; o < O_OUT; o++) {
        const float* r = &sW[o][4 * lane];
        s0[o] = w0.x * r[0] + w0.y * r[1] + w0.z * r[2] + w0.w * r[3];
        s1[o] = w1.x * r[0] + w1.y * r[1] + w1.z * r[2] + w1.w * r[3];
    }
#pragma unroll
    for (int o = 0; o < O_OUT; o++) {
#pragma unroll
        for (int off = 16; off > 0; off >>= 1) {
            s0[o] += __shfl_xor_sync(0xffffffffu, s0[o], off);
            s1[o] += __shfl_xor_sync(0xffffffffu, s1[o], off);
        }
    }
    if (lane == 0) {
#pragma unroll
        for (int o = 0; o < O_OUT; o++) out[(size_t)p0 * O_OUT + o] = s0[o] + sb[o];
    }
    if (lane == 1) {
#pragma unroll
        for (int o = 0; o < O_OUT; o++) out[(size_t)(p0 + 1) * O_OUT + o] = s1[o] + sb[o];
    }
}

// ---------------------------------------------------------------------------
extern "C" void kernel_launch(void* const* d_in, const int* in_sizes, int n_in,
                              void* d_out, int out_size) {
    const float* x    = (const float*)d_in[0];
    const float* W1a  = (const float*)d_in[1];
    const float* b1a  = (const float*)d_in[2];
    const float* W2a  = (const float*)d_in[3];
    const float* b2a  = (const float*)d_in[4];
    const float* g0   = (const float*)d_in[5];
    const float* bt0  = (const float*)d_in[6];
    const float* eps0 = (const float*)d_in[7];
    const float* W1b  = (const float*)d_in[8];
    const float* b1b  = (const float*)d_in[9];
    const float* W2b  = (const float*)d_in[10];
    const float* b2b  = (const float*)d_in[11];
    const float* g1   = (const float*)d_in[12];
    const float* bt1  = (const float*)d_in[13];
    const float* eps1 = (const float*)d_in[14];
    const float* Wl   = (const float*)d_in[15];
    const float* bl   = (const float*)d_in[16];
    const float* Wfc  = (const float*)d_in[17];
    const float* bfc  = (const float*)d_in[18];
    const int* esrc   = (const int*)d_in[19];
    const int* edst   = (const int*)d_in[20];
    const int* pairs  = (const int*)d_in[21];
    float* out = (float*)d_out;

    float* h;
    __nv_bfloat16 *wh, *wl;
    cudaGetSymbolAddress((void**)&h, g_h);
    cudaGetSymbolAddress((void**)&wh, g_wh);
    cudaGetSymbolAddress((void**)&wl, g_wl);

    cudaFuncSetAttribute(k_mlp<0>, cudaFuncAttributeMaxDynamicSharedMemorySize, SMEM_MLP);
    cudaFuncSetAttribute(k_mlp<1>, cudaFuncAttributeMaxDynamicSharedMemorySize, SMEM_MLP);
    cudaFuncSetAttribute(k_gemm_l, cudaFuncAttributeMaxDynamicSharedMemorySize, SMEM_GL);

    const int EB = (E_EDGES + 255) / 256;
    const int GBg = (NPAD * 32 + 255) / 256;
    const int PB = (P_PAIRS / 2 * 32 + 255) / 256;   // 2 pairs per warp
    const int WS = D * D;
    const int PG = 148;

    // prep + CSR build
    k_prep_w<<<(4 * WS + 255) / 256, 256>>>(W1a, W2a, W1b, W2b);
    k_hist<<<EB, 256>>>(edst);
    k_scan<<<1, 1024>>>();
    k_fill<<<EB, 256>>>(esrc, edst);

    // Layer A: gather(x) -> split; MLP -> fp32 h
    k_gather<0><<<GBg, 256>>>(x, eps0);
    k_mlp<0><<<PG, 512, SMEM_MLP>>>(b1a, b2a,
                                    wh + 0 * WS, wl + 0 * WS,
                                    wh + 1 * WS, wl + 1 * WS, h);
    k_bnprep<<<1, 128>>>(g0, bt0);

    // Layer B: gather(h)+BN0 -> split; MLP -> pre-split bf16 (g_ahi/g_alo)
    k_gather<1><<<GBg, 256>>>(h, eps1);
    k_mlp<1><<<PG, 512, SMEM_MLP>>>(b1b, b2b,
                                    wh + 2 * WS, wl + 2 * WS,
                                    wh + 3 * WS, wl + 3 * WS, nullptr);
    k_bnprep<<<1, 128>>>(g1, bt1);

    // Fold BN1 into Wl, then final linear (pure cp.async stage) -> h
    k_prep_l<<<(WS + 255) / 256, 256>>>(Wl, bl);
    k_gemm_l<<<PG, 512, SMEM_GL>>>(wh + 4 * WS, wl + 4 * WS, h);
    k_pairs<<<PB, 256>>>(h, pairs, Wfc, bfc, out);
}

// round 17
// speedup vs baseline: 1.5757x; 1.0005x over previous
#include <cuda_runtime.h>
#include <cuda_bf16.h>
#include <cstdint>

#define N_NODES 50000
#define E_EDGES 600000
#define D 128
#define P_PAIRS 131072
#define O_OUT 7
#define NT64 782                             // ceil(N/64)
#define NPAD (NT64 * 64)                     // 50048

#define HROW_U32 68
#define HARR_U32 (64 * HROW_U32)
#define HARR_BYTES (HARR_U32 * 4)
#define WARR_U32 (128 * HROW_U32)
#define WARR_BYTES (WARR_U32 * 4)
#define SMEM_MLP (4 * HARR_BYTES + 4 * WARR_BYTES)
#define SMEM_GL  (4 * HARR_BYTES + 2 * WARR_BYTES)

// Scratch
__device__ float g_h[N_NODES * D];
__device__ float g_colsum[D];
__device__ float g_colsq[D];
__device__ float g_bn[2 * D];
__device__ float g_bl2[D];                   // folded final bias: Wl@c + bl
__device__ __nv_bfloat16 g_wh[5 * D * D];    // W1a,W2a,W1b,W2b,[Wl*a] (hi)
__device__ __nv_bfloat16 g_wl[5 * D * D];    // (lo)
__device__ __nv_bfloat16 g_ahi[NPAD * D];    // pre-split MLP input (hi)
__device__ __nv_bfloat16 g_alo[NPAD * D];    // (lo)
// CSR (rebuilt every launch)
__device__ int g_deg[N_NODES];
__device__ int g_off[N_NODES + 1];
__device__ int g_cur[N_NODES];
__device__ int g_elist[E_EDGES];

// ---------------------------------------------------------------------------
// prep: split weights; zero deg + stats; histogram edges (4 edges/thread)
// grid must cover max(4*D*D, E/4) threads
// ---------------------------------------------------------------------------
__global__ void k_prep_w(const float* __restrict__ w0, const float* __restrict__ w1,
                         const float* __restrict__ w2, const float* __restrict__ w3,
                         const int* __restrict__ dst) {
    int i = blockIdx.x * blockDim.x + threadIdx.x;
    if (i < N_NODES) g_deg[i] = 0;
    if (i < D) { g_colsum[i] = 0.f; g_colsq[i] = 0.f; }
    if (i < 4 * D * D) {
        const float* srcs[4] = {w0, w1, w2, w3};
        float v = srcs[i >> 14][i & 16383];
        __nv_bfloat16 h = __float2bfloat16(v);
        g_wh[i] = h;
        g_wl[i] = __float2bfloat16(v - __bfloat162float(h));
    }
}

// 4 edges per thread histogram (separate kernel: needs g_deg zeroed first)
__global__ void k_hist(const int* __restrict__ dst) {
    int e0 = (blockIdx.x * blockDim.x + threadIdx.x) * 4;
    if (e0 + 3 < E_EDGES) {
        int4 d4 = *reinterpret_cast<const int4*>(dst + e0);
        atomicAdd(&g_deg[d4.x], 1);
        atomicAdd(&g_deg[d4.y], 1);
        atomicAdd(&g_deg[d4.z], 1);
        atomicAdd(&g_deg[d4.w], 1);
    } else {
        for (int e = e0; e < E_EDGES; e++) atomicAdd(&g_deg[dst[e]], 1);
    }
}

__global__ void __launch_bounds__(1024) k_scan() {
    __shared__ int s_tot[1024];
    const int CH = (N_NODES + 1023) / 1024;
    int t = threadIdx.x;
    int base = t * CH;
    int sum = 0;
    for (int i = 0; i < CH; i++) {
        int idx = base + i;
        if (idx < N_NODES) sum += g_deg[idx];
    }
    s_tot[t] = sum;
    __syncthreads();
    for (int off = 1; off < 1024; off <<= 1) {
        int v = 0;
        if (t >= off) v = s_tot[t - off];
        __syncthreads();
        if (t >= off) s_tot[t] += v;
        __syncthreads();
    }
    int run = (t == 0) ? 0 : s_tot[t - 1];
    for (int i = 0; i < CH; i++) {
        int idx = base + i;
        if (idx < N_NODES) {
            g_off[idx] = run;
            g_cur[idx] = run;
            run += g_deg[idx];
        }
    }
    if (t == 1023) g_off[N_NODES] = s_tot[1023];
}

// 4 edges per thread fill (4 independent atomic chains in flight)
__global__ void k_fill(const int* __restrict__ src, const int* __restrict__ dst) {
    int e0 = (blockIdx.x * blockDim.x + threadIdx.x) * 4;
    if (e0 + 3 < E_EDGES) {
        int4 d4 = *reinterpret_cast<const int4*>(dst + e0);
        int4 s4 = *reinterpret_cast<const int4*>(src + e0);
        int p0 = atomicAdd(&g_cur[d4.x], 1);
        int p1 = atomicAdd(&g_cur[d4.y], 1);
        int p2 = atomicAdd(&g_cur[d4.z], 1);
        int p3 = atomicAdd(&g_cur[d4.w], 1);
        g_elist[p0] = s4.x;
        g_elist[p1] = s4.y;
        g_elist[p2] = s4.z;
        g_elist[p3] = s4.w;
    } else {
        for (int e = e0; e < E_EDGES; e++) {
            int pos = atomicAdd(&g_cur[dst[e]], 1);
            g_elist[pos] = src[e];
        }
    }
}

// ---------------------------------------------------------------------------
static __device__ __forceinline__ uint32_t smem_u32(const void* p) {
    return (uint32_t)__cvta_generic_to_shared(p);
}
static __device__ __forceinline__ void split2(float a, float b, uint32_t& hi, uint32_t& lo) {
    __nv_bfloat162 h = __floats2bfloat162_rn(a, b);
    float ra = a - __bfloat162float(h.x);
    float rb = b - __bfloat162float(h.y);
    __nv_bfloat162 l = __floats2bfloat162_rn(ra, rb);
    hi = *reinterpret_cast<uint32_t*>(&h);
    lo = *reinterpret_cast<uint32_t*>(&l);
}
static __device__ __forceinline__ void ldmx4(uint32_t addr, uint32_t r[4]) {
    asm("ldmatrix.sync.aligned.m8n8.x4.shared.b16 {%0,%1,%2,%3}, [%4];"
        : "=r"(r[0]), "=r"(r[1]), "=r"(r[2]), "=r"(r[3]) : "r"(addr) : "memory");
}
static __device__ __forceinline__ void mma16816(float c[4], const uint32_t a[4],
                                                uint32_t b0, uint32_t b1) {
    asm("mma.sync.aligned.m16n8k16.row.col.f32.bf16.bf16.f32 "
        "{%0,%1,%2,%3},{%4,%5,%6,%7},{%8,%9},{%0,%1,%2,%3};"
        : "+f"(c[0]), "+f"(c[1]), "+f"(c[2]), "+f"(c[3])
        : "r"(a[0]), "r"(a[1]), "r"(a[2]), "r"(a[3]), "r"(b0), "r"(b1));
}
static __device__ __forceinline__ void cpa16(uint32_t dst, const void* src) {
    asm volatile("cp.async.cg.shared.global [%0], [%1], 16;"
                 :: "r"(dst), "l"(src) : "memory");
}
static __device__ __forceinline__ void barg(int id) {
    asm volatile("bar.sync %0, 256;" :: "r"(id) : "memory");
}

// ---------------------------------------------------------------------------
// Fold BN1 affine into final weight: Wl' = Wl ⊙ a (per-col), bias' = Wl@c + bl
// ---------------------------------------------------------------------------
__global__ void k_prep_l(const float* __restrict__ Wl, const float* __restrict__ bl) {
    int i = blockIdx.x * blockDim.x + threadIdx.x;
    if (i < 128 * 32) {
        int j = i >> 5, lane = i & 31;
        const float4* Wr = reinterpret_cast<const float4*>(Wl + j * D);
        float4 w = Wr[lane];
        float4 c = *reinterpret_cast<const float4*>(g_bn + D + lane * 4);
        float s = w.x * c.x + w.y * c.y + w.z * c.z + w.w * c.w;
#pragma unroll
        for (int off = 16; off > 0; off >>= 1)
            s += __shfl_xor_sync(0xffffffffu, s, off);
        if (lane == 0) g_bl2[j] = s + bl[j];
    }
    if (i >= D * D) return;
    int k = i & 127;
    float v = Wl[i] * g_bn[k];
    __nv_bfloat16 h = __float2bfloat16(v);
    g_wh[4 * D * D + i] = h;
    g_wl[4 * D * D + i] = __float2bfloat16(v - __bfloat162float(h));
}

// ---------------------------------------------------------------------------
// Gather + combine + split -> g_ahi/g_alo (bf16 hi/lo). Warp per node.
// ---------------------------------------------------------------------------
template <int AFF>
__global__ void __launch_bounds__(256) k_gather(const float* __restrict__ h,
                                                const float* __restrict__ epsp) {
    int d = (blockIdx.x * blockDim.x + threadIdx.x) >> 5;
    int lane = threadIdx.x & 31;
    if (d >= NPAD) return;
    float4 acc = make_float4(0.f, 0.f, 0.f, 0.f);
    if (d < N_NODES) {
        float cA = 1.0f + *epsp;
        float4 xv = reinterpret_cast<const float4*>(h + (size_t)d * D)[lane];
        acc.x = cA * xv.x; acc.y = cA * xv.y;
        acc.z = cA * xv.z; acc.w = cA * xv.w;
        int beg = g_off[d], end = g_off[d + 1];
        for (int i = beg; i < end; i++) {
            int s = g_elist[i];
            float4 v = reinterpret_cast<const float4*>(h + (size_t)s * D)[lane];
            acc.x += v.x; acc.y += v.y; acc.z += v.z; acc.w += v.w;
        }
        if (AFF) {
            float f = cA + (float)(end - beg);
            float4 a = *reinterpret_cast<const float4*>(g_bn + lane * 4);
            float4 c = *reinterpret_cast<const float4*>(g_bn + D + lane * 4);
            acc.x = a.x * acc.x + f * c.x;
            acc.y = a.y * acc.y + f * c.y;
            acc.z = a.z * acc.z + f * c.z;
            acc.w = a.w * acc.w + f * c.w;
        }
    }
    uint32_t h0, l0, h1, l1;
    split2(acc.x, acc.y, h0, l0);
    split2(acc.z, acc.w, h1, l1);
    size_t base = (size_t)d * D + lane * 4;
    *reinterpret_cast<uint2*>(g_ahi + base) = make_uint2(h0, h1);
    *reinterpret_cast<uint2*>(g_alo + base) = make_uint2(l0, l1);
}

// ---------------------------------------------------------------------------
static __device__ __forceinline__ void mma_3pass(float acc[2][4][4],
                                                 uint32_t Ahi, uint32_t Alo,
                                                 uint32_t Bhi, uint32_t Blo,
                                                 const uint32_t aoff[2],
                                                 const uint32_t boff[2]) {
#pragma unroll
    for (int ks = 0; ks < 8; ks++) {
        uint32_t kb = ks * 32;
        uint32_t ah[2][4], al[2][4], bh[2][4], bl[2][4];
#pragma unroll
        for (int mt = 0; mt < 2; mt++) {
            ldmx4(Ahi + aoff[mt] + kb, ah[mt]);
            ldmx4(Alo + aoff[mt] + kb, al[mt]);
        }
#pragma unroll
        for (int np = 0; np < 2; np++) {
            ldmx4(Bhi + boff[np] + kb, bh[np]);
            ldmx4(Blo + boff[np] + kb, bl[np]);
        }
#pragma unroll
        for (int mt = 0; mt < 2; mt++)
#pragma unroll
            for (int nt = 0; nt < 4; nt++) {
                int np = nt >> 1, o = (nt & 1) * 2;
                mma16816(acc[mt][nt], ah[mt], bh[np][o], bh[np][o + 1]);
            }
#pragma unroll
        for (int mt = 0; mt < 2; mt++)
#pragma unroll
            for (int nt = 0; nt < 4; nt++) {
                int np = nt >> 1, o = (nt & 1) * 2;
                mma16816(acc[mt][nt], ah[mt], bl[np][o], bl[np][o + 1]);
            }
#pragma unroll
        for (int mt = 0; mt < 2; mt++)
#pragma unroll
            for (int nt = 0; nt < 4; nt++) {
                int np = nt >> 1, o = (nt & 1) * 2;
                mma16816(acc[mt][nt], al[mt], bh[np][o], bh[np][o + 1]);
            }
    }
}

static __device__ __forceinline__ void stage_W(const __nv_bfloat16* __restrict__ w,
                                               uint32_t dbase, int t) {
#pragma unroll
    for (int it = 0; it < 4; it++) {
        int c = t + it * 512;
        int row = c >> 4, j = c & 15;
        cpa16(dbase + row * 272 + j * 16, w + row * D + j * 8);
    }
}

// stage one 64-row A tile (hi+lo) via cp.async; t2 in [0,256)
static __device__ __forceinline__ void stage_A_cp(int row0, uint32_t Ahi, uint32_t Alo,
                                                  int t2) {
    const __nv_bfloat16* shi = g_ahi + (size_t)row0 * D;
    const __nv_bfloat16* slo = g_alo + (size_t)row0 * D;
#pragma unroll
    for (int it = 0; it < 4; it++) {
        int c = t2 + it * 256;
        int row = c >> 4, j = c & 15;
        cpa16(Ahi + row * 272 + j * 16, shi + row * D + j * 8);
        cpa16(Alo + row * 272 + j * 16, slo + row * D + j * 8);
    }
    asm volatile("cp.async.commit_group;" ::: "memory");
    asm volatile("cp.async.wait_group 0;" ::: "memory");
}

// ---------------------------------------------------------------------------
// Persistent fused GIN MLP. OUTB16=0: fp32 out. OUTB16=1: pre-split bf16 out.
// ---------------------------------------------------------------------------
template <int OUTB16>
__global__ void __launch_bounds__(512) k_mlp(const float* __restrict__ b1,
                                             const float* __restrict__ b2,
                                             const __nv_bfloat16* __restrict__ w1h,
                                             const __nv_bfloat16* __restrict__ w1l,
                                             const __nv_bfloat16* __restrict__ w2h,
                                             const __nv_bfloat16* __restrict__ w2l,
                                             float* __restrict__ out) {
    extern __shared__ uint32_t smem[];
    __shared__ float sb1[D], sb2[D], s_sum[D], s_sq[D];

    const int t = threadIdx.x;
    const int grp = t >> 8;
    const int t2 = t & 255;
    const int warp8 = t2 >> 5, lane = t & 31;
    const int wm = warp8 & 1, wn = warp8 >> 1;

    uint32_t* As_hi = smem + grp * 2 * HARR_U32;
    uint32_t* As_lo = As_hi + HARR_U32;
    uint32_t* wbase = smem + 4 * HARR_U32;

    if (t < D) {
        sb1[t] = __ldg(b1 + t);
        sb2[t] = __ldg(b2 + t);
        s_sum[t] = 0.f;
        s_sq[t] = 0.f;
    }

    const uint32_t W1h = smem_u32(wbase);
    const uint32_t W1l = smem_u32(wbase + WARR_U32 * 1);
    const uint32_t W2h = smem_u32(wbase + WARR_U32 * 2);
    const uint32_t W2l = smem_u32(wbase + WARR_U32 * 3);
    stage_W(w1h, W1h, t);
    stage_W(w1l, W1l, t);
    stage_W(w2h, W2h, t);
    stage_W(w2l, W2l, t);
    asm volatile("cp.async.commit_group;" ::: "memory");
    asm volatile("cp.async.wait_group 0;" ::: "memory");
    __syncthreads();

    uint32_t aoff[2], boff[2];
#pragma unroll
    for (int mt = 0; mt < 2; mt++) {
        int row = wm * 32 + mt * 16 + ((lane >> 3) & 1) * 8 + (lane & 7);
        aoff[mt] = row * 272 + (lane >> 4) * 16;
    }
#pragma unroll
    for (int np = 0; np < 2; np++) {
        int row = wn * 32 + np * 16 + (lane >> 4) * 8 + (lane & 7);
        boff[np] = row * 272 + ((lane >> 3) & 1) * 16;
    }
    const uint32_t Ahi = smem_u32(As_hi), Alo = smem_u32(As_lo);
    const int lg = lane >> 2;
    const int c2 = (lane & 3) * 2;
    const int bid = 1 + grp;

    int tile = blockIdx.x * 2 + grp;
    const int step = gridDim.x * 2;

    for (; tile < NT64; tile += step) {
        const int row0 = tile * 64;

        stage_A_cp(row0, Ahi, Alo, t2);
        barg(bid);

        float acc[2][4][4];
#pragma unroll
        for (int mt = 0; mt < 2; mt++)
#pragma unroll
            for (int nt = 0; nt < 4; nt++)
#pragma unroll
                for (int i = 0; i < 4; i++) acc[mt][nt][i] = 0.f;

        // ---- GEMM1 ----
        mma_3pass(acc, Ahi, Alo, W1h, W1l, aoff, boff);
        barg(bid);

        // epilogue1: P = relu(acc+b1) -> bf16 hi/lo back into As
#pragma unroll
        for (int mt = 0; mt < 2; mt++) {
            int ra = wm * 32 + mt * 16 + lg;
            int rb = ra + 8;
#pragma unroll
            for (int nt = 0; nt < 4; nt++) {
                int col = wn * 32 + nt * 8 + c2;
                int o = col >> 1;
                float t0 = fmaxf(acc[mt][nt][0] + sb1[col], 0.f);
                float t1 = fmaxf(acc[mt][nt][1] + sb1[col + 1], 0.f);
                float t2v = fmaxf(acc[mt][nt][2] + sb1[col], 0.f);
                float t3 = fmaxf(acc[mt][nt][3] + sb1[col + 1], 0.f);
                uint32_t hi, lo;
                split2(t0, t1, hi, lo);
                As_hi[ra * HROW_U32 + o] = hi;
                As_lo[ra * HROW_U32 + o] = lo;
                split2(t2v, t3, hi, lo);
                As_hi[rb * HROW_U32 + o] = hi;
                As_lo[rb * HROW_U32 + o] = lo;
#pragma unroll
                for (int i = 0; i < 4; i++) acc[mt][nt][i] = 0.f;
            }
        }
        barg(bid);

        // ---- GEMM2 ----
        mma_3pass(acc, Ahi, Alo, W2h, W2l, aoff, boff);
        barg(bid);

        // epilogue2: relu+bias, store, column stats
        {
            float sp[4][2], qp[4][2];
#pragma unroll
            for (int nt = 0; nt < 4; nt++) {
                sp[nt][0] = sp[nt][1] = 0.f;
                qp[nt][0] = qp[nt][1] = 0.f;
            }
#pragma unroll
            for (int mt = 0; mt < 2; mt++) {
                int ra = row0 + wm * 32 + mt * 16 + lg;
                int rb = ra + 8;
#pragma unroll
                for (int nt = 0; nt < 4; nt++) {
                    int col = wn * 32 + nt * 8 + c2;
                    float v0 = fmaxf(acc[mt][nt][0] + sb2[col], 0.f);
                    float v1 = fmaxf(acc[mt][nt][1] + sb2[col + 1], 0.f);
                    float v2 = fmaxf(acc[mt][nt][2] + sb2[col], 0.f);
                    float v3 = fmaxf(acc[mt][nt][3] + sb2[col + 1], 0.f);
                    if (OUTB16) {
                        uint32_t hi = 0, lo = 0;
                        if (ra < N_NODES) {
                            split2(v0, v1, hi, lo);
                            sp[nt][0] += v0; sp[nt][1] += v1;
                            qp[nt][0] += v0 * v0; qp[nt][1] += v1 * v1;
                        }
                        *reinterpret_cast<uint32_t*>(g_ahi + (size_t)ra * D + col) = hi;
                        *reinterpret_cast<uint32_t*>(g_alo + (size_t)ra * D + col) = lo;
                        hi = lo = 0;
                        if (rb < N_NODES) {
                            split2(v2, v3, hi, lo);
                            sp[nt][0] += v2; sp[nt][1] += v3;
                            qp[nt][0] += v2 * v2; qp[nt][1] += v3 * v3;
                        }
                        *reinterpret_cast<uint32_t*>(g_ahi + (size_t)rb * D + col) = hi;
                        *reinterpret_cast<uint32_t*>(g_alo + (size_t)rb * D + col) = lo;
                    } else {
                        if (ra < N_NODES) {
                            *reinterpret_cast<float2*>(out + (size_t)ra * D + col) =
                                make_float2(v0, v1);
                            sp[nt][0] += v0; sp[nt][1] += v1;
                            qp[nt][0] += v0 * v0; qp[nt][1] += v1 * v1;
                        }
                        if (rb < N_NODES) {
                            *reinterpret_cast<float2*>(out + (size_t)rb * D + col) =
                                make_float2(v2, v3);
                            sp[nt][0] += v2; sp[nt][1] += v3;
                            qp[nt][0] += v2 * v2; qp[nt][1] += v3 * v3;
                        }
                    }
                }
            }
#pragma unroll
            for (int nt = 0; nt < 4; nt++) {
#pragma unroll
                for (int d = 4; d < 32; d <<= 1) {
                    sp[nt][0] += __shfl_xor_sync(0xffffffffu, sp[nt][0], d);
                    sp[nt][1] += __shfl_xor_sync(0xffffffffu, sp[nt][1], d);
                    qp[nt][0] += __shfl_xor_sync(0xffffffffu, qp[nt][0], d);
                    qp[nt][1] += __shfl_xor_sync(0xffffffffu, qp[nt][1], d);
                }
            }
            if (lg == 0) {
#pragma unroll
                for (int nt = 0; nt < 4; nt++) {
                    int col = wn * 32 + nt * 8 + c2;
                    atomicAdd(&s_sum[col], sp[nt][0]);
                    atomicAdd(&s_sum[col + 1], sp[nt][1]);
                    atomicAdd(&s_sq[col], qp[nt][0]);
                    atomicAdd(&s_sq[col + 1], qp[nt][1]);
                }
            }
        }
    }

    __syncthreads();
    if (t < D) {
        asm volatile("red.global.add.f32 [%0], %1;" :: "l"(&g_colsum[t]), "f"(s_sum[t]) : "memory");
        asm volatile("red.global.add.f32 [%0], %1;" :: "l"(&g_colsq[t]), "f"(s_sq[t]) : "memory");
    }
}

// ---------------------------------------------------------------------------
// Final linear: out = relu(A@Wl'^T + bias'). A pre-split in g_ahi/g_alo.
// ---------------------------------------------------------------------------
__global__ void __launch_bounds__(512) k_gemm_l(const __nv_bfloat16* __restrict__ wh,
                                                const __nv_bfloat16* __restrict__ wl,
                                                float* __restrict__ out) {
    extern __shared__ uint32_t smem[];
    __shared__ float sb[D];

    const int t = threadIdx.x;
    const int grp = t >> 8;
    const int t2 = t & 255;
    const int warp8 = t2 >> 5, lane = t & 31;
    const int wm = warp8 & 1, wn = warp8 >> 1;

    uint32_t* As_hi = smem + grp * 2 * HARR_U32;
    uint32_t* As_lo = As_hi + HARR_U32;
    uint32_t* wbase = smem + 4 * HARR_U32;

    if (t < D) sb[t] = g_bl2[t];

    const uint32_t Wh = smem_u32(wbase);
    const uint32_t Wl = smem_u32(wbase + WARR_U32);
    stage_W(wh, Wh, t);
    stage_W(wl, Wl, t);
    asm volatile("cp.async.commit_group;" ::: "memory");
    asm volatile("cp.async.wait_group 0;" ::: "memory");
    __syncthreads();

    uint32_t aoff[2], boff[2];
#pragma unroll
    for (int mt = 0; mt < 2; mt++) {
        int row = wm * 32 + mt * 16 + ((lane >> 3) & 1) * 8 + (lane & 7);
        aoff[mt] = row * 272 + (lane >> 4) * 16;
    }
#pragma unroll
    for (int np = 0; np < 2; np++) {
        int row = wn * 32 + np * 16 + (lane >> 4) * 8 + (lane & 7);
        boff[np] = row * 272 + ((lane >> 3) & 1) * 16;
    }
    const uint32_t Ahi = smem_u32(As_hi), Alo = smem_u32(As_lo);
    const int lg = lane >> 2;
    const int c2 = (lane & 3) * 2;
    const int bid = 1 + grp;

    int tile = blockIdx.x * 2 + grp;
    const int step = gridDim.x * 2;

    for (; tile < NT64; tile += step) {
        const int row0 = tile * 64;

        stage_A_cp(row0, Ahi, Alo, t2);
        barg(bid);

        float acc[2][4][4];
#pragma unroll
        for (int mt = 0; mt < 2; mt++)
#pragma unroll
            for (int nt = 0; nt < 4; nt++)
#pragma unroll
                for (int i = 0; i < 4; i++) acc[mt][nt][i] = 0.f;

        mma_3pass(acc, Ahi, Alo, Wh, Wl, aoff, boff);
        barg(bid);

#pragma unroll
        for (int mt = 0; mt < 2; mt++) {
            int ra = row0 + wm * 32 + mt * 16 + lg;
            int rb = ra + 8;
#pragma unroll
            for (int nt = 0; nt < 4; nt++) {
                int col = wn * 32 + nt * 8 + c2;
                if (ra < N_NODES)
                    *reinterpret_cast<float2*>(out + (size_t)ra * D + col) =
                        make_float2(fmaxf(acc[mt][nt][0] + sb[col], 0.f),
                                    fmaxf(acc[mt][nt][1] + sb[col + 1], 0.f));
                if (rb < N_NODES)
                    *reinterpret_cast<float2*>(out + (size_t)rb * D + col) =
                        make_float2(fmaxf(acc[mt][nt][2] + sb[col], 0.f),
                                    fmaxf(acc[mt][nt][3] + sb[col + 1], 0.f));
            }
        }
    }
}

// ---------------------------------------------------------------------------
__global__ void k_bnprep(const float* __restrict__ gamma,
                         const float* __restrict__ beta) {
    int t = threadIdx.x;
    float inv_n = 1.0f / (float)N_NODES;
    float mu = g_colsum[t] * inv_n;
    float var = g_colsq[t] * inv_n - mu * mu;
    float a = gamma[t] * rsqrtf(var + 1e-5f);
    g_bn[t] = a;
    g_bn[D + t] = beta[t] - mu * a;
    g_colsum[t] = 0.f;
    g_colsq[t] = 0.f;
}

// ---------------------------------------------------------------------------
// Pair head: 4 pairs per warp (8 independent row loads in flight)
// ---------------------------------------------------------------------------
__global__ void __launch_bounds__(256) k_pairs(const float* __restrict__ h,
                                               const int* __restrict__ pairs,
                                               const float* __restrict__ Wfc,
                                               const float* __restrict__ bfc,
                                               float* __restrict__ out) {
    __shared__ float sW[O_OUT][D];
    __shared__ float sb[O_OUT];
    int t = threadIdx.x;
    for (int i = t; i < O_OUT * D; i += 256) sW[i / D][i % D] = Wfc[i];
    if (t < O_OUT) sb[t] = bfc[t];
    __syncthreads();

    int w = (blockIdx.x * 256 + t) >> 5;
    int lane = t & 31;
    int p0 = w * 4;
    if (p0 >= P_PAIRS) return;

    float4 wv[4];
#pragma unroll
    for (int k = 0; k < 4; k++) {
        int ia = pairs[2 * (p0 + k)];
        int ib = pairs[2 * (p0 + k) + 1];
        float4 u = reinterpret_cast<const float4*>(h + (size_t)ia * D)[lane];
        float4 v = reinterpret_cast<const float4*>(h + (size_t)ib * D)[lane];
        wv[k] = make_float4(u.x * v.x, u.y * v.y, u.z * v.z, u.w * v.w);
    }

    float s[4][O_OUT];
#pragma unroll
    for (int o = 0; o < O_OUT; o++) {
        const float* r = &sW[o][4 * lane];
#pragma unroll
        for (int k = 0; k < 4; k++)
            s[k][o] = wv[k].x * r[0] + wv[k].y * r[1] + wv[k].z * r[2] + wv[k].w * r[3];
    }
#pragma unroll
    for (int o = 0; o < O_OUT; o++)
#pragma unroll
        for (int off = 16; off > 0; off >>= 1)
#pragma unroll
            for (int k = 0; k < 4; k++)
                s[k][o] += __shfl_xor_sync(0xffffffffu, s[k][o], off);
    if (lane < 4) {
#pragma unroll
        for (int o = 0; o < O_OUT; o++)
            out[(size_t)(p0 + lane) * O_OUT + o] = s[lane][o] + sb[o];
    }
}

// ---------------------------------------------------------------------------
extern "C" void kernel_launch(void* const* d_in, const int* in_sizes, int n_in,
                              void* d_out, int out_size) {
    const float* x    = (const float*)d_in[0];
    const float* W1a  = (const float*)d_in[1];
    const float* b1a  = (const float*)d_in[2];
    const float* W2a  = (const float*)d_in[3];
    const float* b2a  = (const float*)d_in[4];
    const float* g0   = (const float*)d_in[5];
    const float* bt0  = (const float*)d_in[6];
    const float* eps0 = (const float*)d_in[7];
    const float* W1b  = (const float*)d_in[8];
    const float* b1b  = (const float*)d_in[9];
    const float* W2b  = (const float*)d_in[10];
    const float* b2b  = (const float*)d_in[11];
    const float* g1   = (const float*)d_in[12];
    const float* bt1  = (const float*)d_in[13];
    const float* eps1 = (const float*)d_in[14];
    const float* Wl   = (const float*)d_in[15];
    const float* bl   = (const float*)d_in[16];
    const float* Wfc  = (const float*)d_in[17];
    const float* bfc  = (const float*)d_in[18];
    const int* esrc   = (const int*)d_in[19];
    const int* edst   = (const int*)d_in[20];
    const int* pairs  = (const int*)d_in[21];
    float* out = (float*)d_out;

    float* h;
    __nv_bfloat16 *wh, *wl;
    cudaGetSymbolAddress((void**)&h, g_h);
    cudaGetSymbolAddress((void**)&wh, g_wh);
    cudaGetSymbolAddress((void**)&wl, g_wl);

    cudaFuncSetAttribute(k_mlp<0>, cudaFuncAttributeMaxDynamicSharedMemorySize, SMEM_MLP);
    cudaFuncSetAttribute(k_mlp<1>, cudaFuncAttributeMaxDynamicSharedMemorySize, SMEM_MLP);
    cudaFuncSetAttribute(k_gemm_l, cudaFuncAttributeMaxDynamicSharedMemorySize, SMEM_GL);

    const int E4B = (E_EDGES / 4 + 255) / 256;        // 4 edges/thread
    const int GBg = (NPAD * 32 + 255) / 256;
    const int PB = (P_PAIRS / 4 * 32 + 255) / 256;    // 4 pairs per warp
    const int WS = D * D;
    const int PG = 148;

    // prep + CSR build
    k_prep_w<<<(4 * WS + 255) / 256, 256>>>(W1a, W2a, W1b, W2b, edst);
    k_hist<<<E4B, 256>>>(edst);
    k_scan<<<1, 1024>>>();
    k_fill<<<E4B, 256>>>(esrc, edst);

    // Layer A: gather(x) -> split; MLP -> fp32 h
    k_gather<0><<<GBg, 256>>>(x, eps0);
    k_mlp<0><<<PG, 512, SMEM_MLP>>>(b1a, b2a,
                                    wh + 0 * WS, wl + 0 * WS,
                                    wh + 1 * WS, wl + 1 * WS, h);
    k_bnprep<<<1, 128>>>(g0, bt0);

    // Layer B: gather(h)+BN0 -> split; MLP -> pre-split bf16 (g_ahi/g_alo)
    k_gather<1><<<GBg, 256>>>(h, eps1);
    k_mlp<1><<<PG, 512, SMEM_MLP>>>(b1b, b2b,
                                    wh + 2 * WS, wl + 2 * WS,
                                    wh + 3 * WS, wl + 3 * WS, nullptr);
    k_bnprep<<<1, 128>>>(g1, bt1);

    // Fold BN1 into Wl, then final linear (pure cp.async stage) -> h
    k_prep_l<<<(WS + 255) / 256, 256>>>(Wl, bl);
    k_gemm_l<<<PG, 512, SMEM_GL>>>(wh + 4 * WS, wl + 4 * WS, h);
    k_pairs<<<PB, 256>>>(h, pairs, Wfc, bfc, out);
}